// round 11
// baseline (speedup 1.0000x reference)
#include <cuda_runtime.h>
#include <cuda_fp16.h>
#include <cstdint>
#include <math.h>

#define NN 100000

// ---------------- scratch ----------------
__device__ __half g_Xh [(size_t)NN * 128];     // fp16 x
__device__ __half g_Qh [(size_t)NN * 128];     // fp16 Q
__device__ __half g_Vh [(size_t)5 * NN * 128]; // fp16 V_r
__device__ float  g_E  [(size_t)NN * 20];
__device__ float  g_H  [(size_t)NN * 128];     // exact H (residual for FFN2)
__device__ __half g_Hth[(size_t)NN * 128];     // fp16 H
__device__ __half g_Fh [(size_t)NN * 512];     // fp16 FFN intermediate
__device__ __half g_WQh [128 * 128];           // [c][k]
__device__ __half g_WKVh[5 * 256 * 128];       // [r][c(K:0-127,V:128-255)][k]
__device__ __half g_W1h [512 * 128];
__device__ __half g_W2h [128 * 512];
__device__ float  g_denom[20];

__device__ __forceinline__ uint32_t smem_u32(const void* p) {
    uint32_t a;
    asm("{ .reg .u64 t; cvta.to.shared.u64 t, %1; cvt.u32.u64 %0, t; }" : "=r"(a) : "l"(p));
    return a;
}
__device__ __forceinline__ void cpa16(uint32_t dst, const void* src) {
    asm volatile("cp.async.ca.shared.global [%0], [%1], 16;" :: "r"(dst), "l"(src));
}

__global__ void zero_denoms_kernel() {
    if (threadIdx.x < 20) g_denom[threadIdx.x] = 0.0f;
}

__global__ void conv_x_kernel(const float* __restrict__ x) {
    size_t i = ((size_t)blockIdx.x * 256 + threadIdx.x) * 4;
    if (i >= (size_t)NN * 128) return;
    float4 v = *(const float4*)(x + i);
    *(__half2*)(g_Xh + i)     = __floats2half2_rn(v.x, v.y);
    *(__half2*)(g_Xh + i + 2) = __floats2half2_rn(v.z, v.w);
}

// wk/wv -> g_WKVh[r][c][k], K cols 0-127, V cols 128-255
__global__ void transA_kernel(const float* __restrict__ wk, const float* __restrict__ wv) {
    int z = blockIdx.z;
    int idx = blockIdx.x * 256 + threadIdx.x;     // < 32768
    int c = idx >> 7, k = idx & 127;
    float v;
    if (c < 128) {
        v = wk[(size_t)(c >> 5) * 20480 + (size_t)z * 4096 + k * 32 + (c & 31)];
    } else {
        int c2 = c - 128;
        v = wv[(size_t)(c2 >> 5) * 20480 + (size_t)z * 4096 + k * 32 + (c2 & 31)];
    }
    g_WKVh[(size_t)z * 32768 + idx] = __float2half_rn(v);
}

// wq / W1 / W2 transposes merged
__global__ void transB_kernel(const float* __restrict__ wq,
                              const float* __restrict__ W1,
                              const float* __restrict__ W2) {
    int b = blockIdx.x;
    int tid = threadIdx.x;
    if (b < 64) {
        int idx = b * 256 + tid;                  // < 16384
        int c = idx >> 7, k = idx & 127;
        g_WQh[idx] = __float2half_rn(wq[(size_t)(c >> 5) * 4096 + k * 32 + (c & 31)]);
    } else if (b < 320) {
        int idx = (b - 64) * 256 + tid;           // < 65536, [c(512)][k(128)]
        int c = idx >> 7, k = idx & 127;
        g_W1h[idx] = __float2half_rn(W1[(size_t)k * 512 + c]);
    } else {
        int idx = (b - 320) * 256 + tid;          // < 65536, [c(128)][k(512)]
        int c = idx >> 9, k = idx & 511;
        g_W2h[idx] = __float2half_rn(W2[(size_t)k * 128 + c]);
    }
}

#define LDM_X4(r0,r1,r2,r3,addr) \
    asm volatile("ldmatrix.sync.aligned.m8n8.x4.shared.b16 {%0,%1,%2,%3}, [%4];" \
                 : "=r"(r0), "=r"(r1), "=r"(r2), "=r"(r3) : "r"(addr))
#define MMA_F16(dd,aa,bb) \
    asm volatile("mma.sync.aligned.m16n8k16.row.col.f32.f16.f16.f32 " \
                 "{%0,%1,%2,%3}, {%4,%5,%6,%7}, {%8,%9}, {%0,%1,%2,%3};" \
                 : "+f"((dd)[0]), "+f"((dd)[1]), "+f"((dd)[2]), "+f"((dd)[3]) \
                 : "r"((aa)[0]), "r"((aa)[1]), "r"((aa)[2]), "r"((aa)[3]), \
                   "r"((bb)[0]), "r"((bb)[1]))

// ================= shared mainloop (256-thread kernels) ==========
template<typename STAGEF>
__device__ __forceinline__ void mainloop(uint32_t sbase, int kchunks, STAGEF stage,
                                         int m0w, int n0w, int lane,
                                         float d[2][8][4]) {
    const int lrow = lane & 7;
    const int a_hi = (lane >> 3) >> 1, a_roff = ((lane >> 3) & 1) * 8;
    const int b_hi = (lane >> 3) & 1,  b_coff = (lane >> 4) * 8;
    stage(0, 0);
    for (int kc = 0; kc < kchunks; ++kc) {
        const int bsel = kc & 1;
        if (kc + 1 < kchunks) { stage(bsel ^ 1, kc + 1);
            asm volatile("cp.async.wait_group 1;" ::: "memory");
        } else { asm volatile("cp.async.wait_group 0;" ::: "memory"); }
        __syncthreads();
        const uint32_t abase = sbase + (uint32_t)bsel * 16384u;
        const uint32_t bbase = sbase + 32768u + (uint32_t)bsel * 16384u;
#pragma unroll
        for (int ks = 0; ks < 4; ++ks) {
            uint32_t a[2][4], b[8][2];
#pragma unroll
            for (int mf = 0; mf < 2; ++mf) {
                int r = m0w + mf * 16 + lrow + a_roff;
                uint32_t addr = abase + (uint32_t)r * 128u
                              + (uint32_t)(((2 * ks + a_hi) ^ lrow) << 4);
                LDM_X4(a[mf][0], a[mf][1], a[mf][2], a[mf][3], addr);
            }
#pragma unroll
            for (int pr = 0; pr < 4; ++pr) {
                int c = n0w + pr * 16 + lrow + b_coff;
                uint32_t addr = bbase + (uint32_t)c * 128u
                              + (uint32_t)(((2 * ks + b_hi) ^ (c & 7)) << 4);
                LDM_X4(b[2*pr][0], b[2*pr][1], b[2*pr+1][0], b[2*pr+1][1], addr);
            }
#pragma unroll
            for (int mf = 0; mf < 2; ++mf)
#pragma unroll
                for (int nf = 0; nf < 8; ++nf) MMA_F16(d[mf][nf], a[mf], b[nf]);
        }
        __syncthreads();
    }
}

__device__ __forceinline__ void stage_acc(float* sC, int m0w, int n0w, int lane,
                                          float d[2][8][4]) {
    const int g4 = lane >> 2, t4 = lane & 3;
#pragma unroll
    for (int mf = 0; mf < 2; ++mf)
#pragma unroll
        for (int nf = 0; nf < 8; ++nf) {
            int row = m0w + mf * 16 + g4;
            int col = n0w + nf * 8 + t4 * 2;
            *(float2*)(sC + row * 132 + col)       = make_float2(d[mf][nf][0], d[mf][nf][1]);
            *(float2*)(sC + (row + 8) * 132 + col) = make_float2(d[mf][nf][2], d[mf][nf][3]);
        }
}

// ---------------- generic fp16 GEMM (Q / FFN1 / FFN2), 256 threads -----------
// epi: 1 bias+relu fp16, 2 bias+resid+LN f32, 3 plain fp16
__global__ __launch_bounds__(256, 2)
void tgemm(const __half* __restrict__ A, int Astride,
           const __half* __restrict__ BT, int Kb,
           int kchunks,
           float* __restrict__ C, __half* __restrict__ Ch, int Cstride,
           int epi,
           const float* __restrict__ bias,
           const float* __restrict__ resid,
           const float* __restrict__ gamma,
           const float* __restrict__ beta)
{
    extern __shared__ uint32_t sm[];
    char* smc = (char*)sm;
    const uint32_t sbase = smem_u32(smc);

    const int tid  = threadIdx.x;
    const int wid  = tid >> 5;
    const int lane = tid & 31;
    const int cg0  = blockIdx.y * 128;
    const int m0   = blockIdx.x * 128;
    const int m0w  = (wid >> 1) * 32;
    const int n0w  = (wid & 1) * 64;

    const int srow = tid >> 3, schk = tid & 7;
    float d[2][8][4];
#pragma unroll
    for (int i = 0; i < 2; i++)
#pragma unroll
        for (int j = 0; j < 8; j++)
#pragma unroll
            for (int q = 0; q < 4; q++) d[i][j][q] = 0.0f;

    auto stage = [&](int bsel, int kc) {
        const int kg0 = kc * 64;
        uint32_t abase = sbase + (uint32_t)bsel * 16384u;
        uint32_t bbase = sbase + 32768u + (uint32_t)bsel * 16384u;
#pragma unroll
        for (int p = 0; p < 4; ++p) {
            int row = srow + p * 32;
            int ar  = m0 + row; if (ar >= NN) ar = NN - 1;
            uint32_t off = (uint32_t)row * 128u + (uint32_t)((schk ^ (row & 7)) << 4);
            cpa16(abase + off, A + (size_t)ar * Astride + kg0 + schk * 8);
            cpa16(bbase + off, BT + (size_t)(cg0 + row) * Kb + kg0 + schk * 8);
        }
        asm volatile("cp.async.commit_group;" ::: "memory");
    };

    mainloop(sbase, kchunks, stage, m0w, n0w, lane, d);

    float* sC = (float*)sm;
    stage_acc(sC, m0w, n0w, lane, d);
    __syncthreads();

    if (epi == 2) {
        for (int rr = wid; rr < 128; rr += 8) {
            int gr = m0 + rr;
            if (gr >= NN) continue;
            const float* rp = resid + (size_t)gr * 128;
            float v0 = sC[rr * 132 + lane]      + bias[lane]      + rp[lane];
            float v1 = sC[rr * 132 + 32 + lane] + bias[32 + lane] + rp[32 + lane];
            float v2 = sC[rr * 132 + 64 + lane] + bias[64 + lane] + rp[64 + lane];
            float v3 = sC[rr * 132 + 96 + lane] + bias[96 + lane] + rp[96 + lane];
            float s1 = v0 + v1 + v2 + v3;
            float s2 = v0 * v0 + v1 * v1 + v2 * v2 + v3 * v3;
#pragma unroll
            for (int o = 16; o > 0; o >>= 1) {
                s1 += __shfl_xor_sync(0xffffffffu, s1, o);
                s2 += __shfl_xor_sync(0xffffffffu, s2, o);
            }
            float mu  = s1 * (1.0f / 128.0f);
            float var = s2 * (1.0f / 128.0f) - mu * mu;
            float rs  = rsqrtf(var + 1e-5f);
            float* dst = C + (size_t)gr * 128;
            dst[lane]      = (v0 - mu) * rs * gamma[lane]      + beta[lane];
            dst[lane + 32] = (v1 - mu) * rs * gamma[lane + 32] + beta[lane + 32];
            dst[lane + 64] = (v2 - mu) * rs * gamma[lane + 64] + beta[lane + 64];
            dst[lane + 96] = (v3 - mu) * rs * gamma[lane + 96] + beta[lane + 96];
        }
    } else {
#pragma unroll
        for (int p = 0; p < 4; ++p) {
            int i   = tid + p * 256;
            int row = i >> 3;
            int q   = (i & 7) << 4;
            int gr  = m0 + row;
            if (gr >= NN) continue;
            __half hb[16];
#pragma unroll
            for (int h = 0; h < 4; ++h) {
                int c = q + h * 4;
                float4 v = *(const float4*)(sC + row * 132 + c);
                if (epi == 1) {
                    int cg = cg0 + c;
                    v.x = fmaxf(v.x + bias[cg + 0], 0.f);
                    v.y = fmaxf(v.y + bias[cg + 1], 0.f);
                    v.z = fmaxf(v.z + bias[cg + 2], 0.f);
                    v.w = fmaxf(v.w + bias[cg + 3], 0.f);
                }
                hb[h*4+0] = __float2half_rn(v.x);
                hb[h*4+1] = __float2half_rn(v.y);
                hb[h*4+2] = __float2half_rn(v.z);
                hb[h*4+3] = __float2half_rn(v.w);
            }
            __half* dst = Ch + (size_t)gr * Cstride + cg0 + q;
            *(uint4*)(dst)     = *(uint4*)(hb);
            *(uint4*)(dst + 8) = *(uint4*)(hb + 8);
        }
    }
}

// ---------------- fused K+V GEMM (128x256 tile, 512 threads) ------------------
// B = [Wk_r || Wv_r]. Epilogue: logits+denoms from K cols, fp16 V store.
__global__ __launch_bounds__(512, 1)
void kvgemm(const int* __restrict__ nbr)
{
    extern __shared__ uint32_t sm[];
    char* smc = (char*)sm;
    const uint32_t sbase = smem_u32(smc);
    __shared__ int rowg[128];
    __shared__ float sden[20];

    const int tid  = threadIdx.x;
    const int wid  = tid >> 5;          // 0..15
    const int lane = tid & 31;
    const int z    = blockIdx.z;
    const int m0   = blockIdx.x * 128;
    const int m0w  = (wid >> 2) * 32;   // 4 m-rows of warps
    const int n0w  = (wid & 3) * 64;    // 4 n-cols of warps (0..192)

    if (tid < 128) {
        int gr  = m0 + tid;
        int idx = (gr < NN) ? gr : (NN - 1);
        if (z > 0 && gr < NN) idx = nbr[gr * 4 + (z - 1)];
        rowg[tid] = idx;
    }
    if (tid < 20) sden[tid] = 0.0f;
    __syncthreads();

    const __half* Bz = g_WKVh + (size_t)z * 32768;

    float d[2][8][4];
#pragma unroll
    for (int i = 0; i < 2; i++)
#pragma unroll
        for (int j = 0; j < 8; j++)
#pragma unroll
            for (int q = 0; q < 4; q++) d[i][j][q] = 0.0f;

    // smem: A buffers [0,16K),[16K,32K) ; B buffers [32K,64K),[64K,96K)
    auto stage = [&](int bsel, int kc) {
        const int kg0 = kc * 64;
        uint32_t abase = sbase + (uint32_t)bsel * 16384u;
        uint32_t bbase = sbase + 32768u + (uint32_t)bsel * 32768u;
#pragma unroll
        for (int p = 0; p < 2; ++p) {          // A: 128 rows x 8 chunks
            int i   = tid + p * 512;
            int row = i >> 3, chk = i & 7;
            uint32_t off = (uint32_t)row * 128u + (uint32_t)((chk ^ (row & 7)) << 4);
            cpa16(abase + off, g_Xh + (size_t)rowg[row] * 128 + kg0 + chk * 8);
        }
#pragma unroll
        for (int p = 0; p < 4; ++p) {          // B: 256 rows x 8 chunks
            int i   = tid + p * 512;
            int row = i >> 3, chk = i & 7;
            uint32_t off = (uint32_t)row * 128u + (uint32_t)((chk ^ (row & 7)) << 4);
            cpa16(bbase + off, Bz + (size_t)row * 128 + kg0 + chk * 8);
        }
        asm volatile("cp.async.commit_group;" ::: "memory");
    };

    const int lrow = lane & 7;
    const int a_hi = (lane >> 3) >> 1, a_roff = ((lane >> 3) & 1) * 8;
    const int b_hi = (lane >> 3) & 1,  b_coff = (lane >> 4) * 8;

    stage(0, 0);
    for (int kc = 0; kc < 2; ++kc) {
        const int bsel = kc & 1;
        if (kc + 1 < 2) { stage(bsel ^ 1, kc + 1);
            asm volatile("cp.async.wait_group 1;" ::: "memory");
        } else { asm volatile("cp.async.wait_group 0;" ::: "memory"); }
        __syncthreads();
        const uint32_t abase = sbase + (uint32_t)bsel * 16384u;
        const uint32_t bbase = sbase + 32768u + (uint32_t)bsel * 32768u;
#pragma unroll
        for (int ks = 0; ks < 4; ++ks) {
            uint32_t a[2][4], b[8][2];
#pragma unroll
            for (int mf = 0; mf < 2; ++mf) {
                int r = m0w + mf * 16 + lrow + a_roff;
                uint32_t addr = abase + (uint32_t)r * 128u
                              + (uint32_t)(((2 * ks + a_hi) ^ lrow) << 4);
                LDM_X4(a[mf][0], a[mf][1], a[mf][2], a[mf][3], addr);
            }
#pragma unroll
            for (int pr = 0; pr < 4; ++pr) {
                int c = n0w + pr * 16 + lrow + b_coff;
                uint32_t addr = bbase + (uint32_t)c * 128u
                              + (uint32_t)(((2 * ks + b_hi) ^ (c & 7)) << 4);
                LDM_X4(b[2*pr][0], b[2*pr][1], b[2*pr+1][0], b[2*pr+1][1], addr);
            }
#pragma unroll
            for (int mf = 0; mf < 2; ++mf)
#pragma unroll
                for (int nf = 0; nf < 8; ++nf) MMA_F16(d[mf][nf], a[mf], b[nf]);
        }
        __syncthreads();
    }

    float* sC = (float*)sm;

    // ---- phase a: K warps stage, fused logits + denominators ----
    if ((wid & 3) < 2) stage_acc(sC, m0w, n0w, lane, d);
    __syncthreads();

    const float scale = 0.1767766952966369f;   // 1/sqrt(32)
    float esum[4] = {0.f, 0.f, 0.f, 0.f};
    for (int rr = wid; rr < 128; rr += 16) {
        int gr = m0 + rr;
        if (gr >= NN) continue;
        const __half* qp = g_Qh + (size_t)gr * 128;
#pragma unroll
        for (int h = 0; h < 4; ++h) {
            float s = sC[rr * 132 + h * 32 + lane] * __half2float(qp[h * 32 + lane]);
#pragma unroll
            for (int o = 16; o > 0; o >>= 1) s += __shfl_xor_sync(0xffffffffu, s, o);
            if (lane == 0) {
                float e = expf(s * scale);
                g_E[(size_t)gr * 20 + h * 5 + z] = e;
                esum[h] += e;
            }
        }
    }
    if (lane == 0) {
#pragma unroll
        for (int h = 0; h < 4; ++h) atomicAdd(&sden[h * 5 + z], esum[h]);
    }
    __syncthreads();
    if (tid < 20 && sden[tid] != 0.0f) atomicAdd(&g_denom[tid], sden[tid]);

    // ---- phase b: V warps stage (cols n0w-128), fp16 store ----
    if ((wid & 3) >= 2) stage_acc(sC, m0w, n0w - 128, lane, d);
    __syncthreads();

#pragma unroll
    for (int p = 0; p < 2; ++p) {
        int i   = tid + p * 512;
        int row = i >> 3;
        int q   = (i & 7) << 4;
        int gr  = m0 + row;
        if (gr >= NN) continue;
        __half hb[16];
#pragma unroll
        for (int h = 0; h < 4; ++h) {
            int c = q + h * 4;
            float4 v = *(const float4*)(sC + row * 132 + c);
            hb[h*4+0] = __float2half_rn(v.x);
            hb[h*4+1] = __float2half_rn(v.y);
            hb[h*4+2] = __float2half_rn(v.z);
            hb[h*4+3] = __float2half_rn(v.w);
        }
        __half* dst = g_Vh + ((size_t)z * NN + gr) * 128 + q;
        *(uint4*)(dst)     = *(uint4*)(hb);
        *(uint4*)(dst + 8) = *(uint4*)(hb + 8);
    }
}

// ---------------- combine + residual + LN1 (reads fp16 V) ----------------
__global__ void combine_ln1_kernel(const float* __restrict__ x,
                                   const float* __restrict__ g1,
                                   const float* __restrict__ be1) {
    __shared__ float sinv[20];
    const int tid = threadIdx.x;
    if (tid < 20) sinv[tid] = 1.0f / g_denom[tid];
    __syncthreads();
    const int n    = blockIdx.x * 8 + (tid >> 5);
    const int lane = tid & 31;
    if (n >= NN) return;
    float t[4];
    float s1 = 0.0f, s2 = 0.0f;
#pragma unroll
    for (int h = 0; h < 4; h++) {
        float z = 0.0f;
#pragma unroll
        for (int r = 0; r < 5; r++) {
            float p = g_E[(size_t)n * 20 + h * 5 + r] * sinv[h * 5 + r];
            z = fmaf(p, __half2float(g_Vh[((size_t)r * NN + n) * 128 + h * 32 + lane]), z);
        }
        float v = x[(size_t)n * 128 + h * 32 + lane] + z;
        t[h] = v;
        s1 += v;
        s2 = fmaf(v, v, s2);
    }
#pragma unroll
    for (int o = 16; o > 0; o >>= 1) {
        s1 += __shfl_xor_sync(0xffffffffu, s1, o);
        s2 += __shfl_xor_sync(0xffffffffu, s2, o);
    }
    float mu  = s1 * (1.0f / 128.0f);
    float var = s2 * (1.0f / 128.0f) - mu * mu;
    float rs  = rsqrtf(var + 1e-5f);
#pragma unroll
    for (int h = 0; h < 4; h++) {
        int c = h * 32 + lane;
        float hv = (t[h] - mu) * rs * g1[c] + be1[c];
        g_H  [(size_t)n * 128 + c] = hv;
        g_Hth[(size_t)n * 128 + c] = __float2half_rn(hv);
    }
}

// ---------------- launch ----------------
extern "C" void kernel_launch(void* const* d_in, const int* in_sizes, int n_in,
                              void* d_out, int out_size)
{
    const float* x   = (const float*)d_in[0];
    const int*   nbr = (const int*)  d_in[1];
    const float* wq  = (const float*)d_in[2];
    const float* wk  = (const float*)d_in[3];
    const float* wv  = (const float*)d_in[4];
    const float* W1  = (const float*)d_in[5];
    const float* b1  = (const float*)d_in[6];
    const float* W2  = (const float*)d_in[7];
    const float* b2  = (const float*)d_in[8];
    const float* g1  = (const float*)d_in[9];
    const float* be1 = (const float*)d_in[10];
    const float* g2  = (const float*)d_in[11];
    const float* be2 = (const float*)d_in[12];
    float* out = (float*)d_out;

    void *pXh, *pQh, *pH, *pHth, *pFh, *pWQ, *pW1, *pW2;
    cudaGetSymbolAddress(&pXh, g_Xh);
    cudaGetSymbolAddress(&pQh, g_Qh);
    cudaGetSymbolAddress(&pH,  g_H);
    cudaGetSymbolAddress(&pHth, g_Hth);
    cudaGetSymbolAddress(&pFh, g_Fh);
    cudaGetSymbolAddress(&pWQ, g_WQh);
    cudaGetSymbolAddress(&pW1, g_W1h);
    cudaGetSymbolAddress(&pW2, g_W2h);

    const size_t SMEMSZ  = (size_t)128 * 132 * sizeof(float);   // 67584 (tgemm)
    const size_t SMEMKV  = 98304;                               // 96KB (kvgemm)
    cudaFuncSetAttribute((const void*)tgemm,
                         cudaFuncAttributeMaxDynamicSharedMemorySize, (int)SMEMSZ);
    cudaFuncSetAttribute((const void*)kvgemm,
                         cudaFuncAttributeMaxDynamicSharedMemorySize, (int)SMEMKV);

    const int GN = (NN + 127) / 128;   // 782

    zero_denoms_kernel<<<1, 32>>>();                       // 1
    conv_x_kernel<<<12500, 256>>>(x);                      // 2
    transA_kernel<<<dim3(128, 1, 5), 256>>>(wk, wv);       // 3
    transB_kernel<<<576, 256>>>(wq, W1, W2);               // 4

    // 5: Q = Xh @ Wq -> g_Qh (fp16)
    tgemm<<<dim3(GN, 1, 1), 256, SMEMSZ>>>(
        (const __half*)pXh, 128, (const __half*)pWQ, 128, 2,
        nullptr, (__half*)pQh, 128, 3, nullptr, nullptr, nullptr, nullptr);

    // 6: fused K+V GEMM + logits + denoms + V store (profiled by ncu -s 5)
    kvgemm<<<dim3(GN, 1, 5), 512, SMEMKV>>>(nbr);

    // 7: combine + residual + LN1
    combine_ln1_kernel<<<NN / 8, 256>>>(x, g1, be1);

    // 8: FFN1: relu(Hth @ W1 + b1) -> g_Fh (fp16)
    tgemm<<<dim3(GN, 4, 1), 256, SMEMSZ>>>(
        (const __half*)pHth, 128, (const __half*)pW1, 128, 2,
        nullptr, (__half*)pFh, 512, 1, b1, nullptr, nullptr, nullptr);

    // 9: FFN2 + resid(H exact) + LN2 -> out
    tgemm<<<dim3(GN, 1, 1), 256, SMEMSZ>>>(
        (const __half*)pFh, 512, (const __half*)pW2, 512, 8,
        out, nullptr, 128, 2, b2, (const float*)pH, g2, be2);
}

// round 12
// speedup vs baseline: 1.0501x; 1.0501x over previous
#include <cuda_runtime.h>
#include <cuda_fp16.h>
#include <cstdint>
#include <math.h>

#define NN 100000

// ---------------- scratch ----------------
__device__ __half g_Xh [(size_t)NN * 128];
__device__ __half g_Qh [(size_t)NN * 128];
__device__ __half g_Vh [(size_t)5 * NN * 128];
__device__ float  g_E  [(size_t)NN * 20];
__device__ float  g_H  [(size_t)NN * 128];
__device__ __half g_Hth[(size_t)NN * 128];
__device__ __half g_Fh [(size_t)NN * 512];
__device__ __half g_WQh [128 * 128];
__device__ __half g_WKVh[5 * 256 * 128];   // [r][c(K:0-127,V:128-255)][k]
__device__ __half g_W1h [512 * 128];
__device__ __half g_W2h [128 * 512];
__device__ float  g_denom[20];

__device__ __forceinline__ uint32_t smem_u32(const void* p) {
    uint32_t a;
    asm("{ .reg .u64 t; cvta.to.shared.u64 t, %1; cvt.u32.u64 %0, t; }" : "=r"(a) : "l"(p));
    return a;
}
__device__ __forceinline__ void cpa16(uint32_t dst, const void* src) {
    asm volatile("cp.async.ca.shared.global [%0], [%1], 16;" :: "r"(dst), "l"(src));
}

__global__ void conv_x_kernel(const float* __restrict__ x) {
    if (blockIdx.x == 0 && threadIdx.x < 20) g_denom[threadIdx.x] = 0.0f;
    size_t i = ((size_t)blockIdx.x * 256 + threadIdx.x) * 4;
    if (i >= (size_t)NN * 128) return;
    float4 v = *(const float4*)(x + i);
    *(__half2*)(g_Xh + i)     = __floats2half2_rn(v.x, v.y);
    *(__half2*)(g_Xh + i + 2) = __floats2half2_rn(v.z, v.w);
}

// all weight transposes in one launch (grid = 640 + 576)
__global__ void trans_all(const float* __restrict__ wk, const float* __restrict__ wv,
                          const float* __restrict__ wq, const float* __restrict__ W1,
                          const float* __restrict__ W2) {
    int b = blockIdx.x;
    int tid = threadIdx.x;
    if (b < 640) {
        int z = b >> 7;
        int idx = (b & 127) * 256 + tid;          // < 32768
        int c = idx >> 7, k = idx & 127;
        float v;
        if (c < 128) {
            v = wk[(size_t)(c >> 5) * 20480 + (size_t)z * 4096 + k * 32 + (c & 31)];
        } else {
            int c2 = c - 128;
            v = wv[(size_t)(c2 >> 5) * 20480 + (size_t)z * 4096 + k * 32 + (c2 & 31)];
        }
        g_WKVh[(size_t)z * 32768 + idx] = __float2half_rn(v);
    } else {
        int b2 = b - 640;
        if (b2 < 64) {
            int idx = b2 * 256 + tid;             // < 16384
            int c = idx >> 7, k = idx & 127;
            g_WQh[idx] = __float2half_rn(wq[(size_t)(c >> 5) * 4096 + k * 32 + (c & 31)]);
        } else if (b2 < 320) {
            int idx = (b2 - 64) * 256 + tid;      // < 65536 [c512][k128]
            int c = idx >> 7, k = idx & 127;
            g_W1h[idx] = __float2half_rn(W1[(size_t)k * 512 + c]);
        } else {
            int idx = (b2 - 320) * 256 + tid;     // < 65536 [c128][k512]
            int c = idx >> 9, k = idx & 511;
            g_W2h[idx] = __float2half_rn(W2[(size_t)k * 128 + c]);
        }
    }
}

#define LDM_X4(r0,r1,r2,r3,addr) \
    asm volatile("ldmatrix.sync.aligned.m8n8.x4.shared.b16 {%0,%1,%2,%3}, [%4];" \
                 : "=r"(r0), "=r"(r1), "=r"(r2), "=r"(r3) : "r"(addr))
#define MMA_F16(dd,aa,bb) \
    asm volatile("mma.sync.aligned.m16n8k16.row.col.f32.f16.f16.f32 " \
                 "{%0,%1,%2,%3}, {%4,%5,%6,%7}, {%8,%9}, {%0,%1,%2,%3};" \
                 : "+f"((dd)[0]), "+f"((dd)[1]), "+f"((dd)[2]), "+f"((dd)[3]) \
                 : "r"((aa)[0]), "r"((aa)[1]), "r"((aa)[2]), "r"((aa)[3]), \
                   "r"((bb)[0]), "r"((bb)[1]))

// compute one 64-k chunk (fixed A buf at abase, B buf at bbase)
__device__ __forceinline__ void chunk_mma(uint32_t abase, uint32_t bbase,
                                          int m0w, int n0w, int lane,
                                          float d[2][8][4]) {
    const int lrow = lane & 7;
    const int a_hi = (lane >> 3) >> 1, a_roff = ((lane >> 3) & 1) * 8;
    const int b_hi = (lane >> 3) & 1,  b_coff = (lane >> 4) * 8;
#pragma unroll
    for (int ks = 0; ks < 4; ++ks) {
        uint32_t a[2][4], b[8][2];
#pragma unroll
        for (int mf = 0; mf < 2; ++mf) {
            int r = m0w + mf * 16 + lrow + a_roff;
            uint32_t addr = abase + (uint32_t)r * 128u
                          + (uint32_t)(((2 * ks + a_hi) ^ lrow) << 4);
            LDM_X4(a[mf][0], a[mf][1], a[mf][2], a[mf][3], addr);
        }
#pragma unroll
        for (int pr = 0; pr < 4; ++pr) {
            int c = n0w + pr * 16 + lrow + b_coff;
            uint32_t addr = bbase + (uint32_t)c * 128u
                          + (uint32_t)(((2 * ks + b_hi) ^ (c & 7)) << 4);
            LDM_X4(b[2*pr][0], b[2*pr][1], b[2*pr+1][0], b[2*pr+1][1], addr);
        }
#pragma unroll
        for (int mf = 0; mf < 2; ++mf)
#pragma unroll
            for (int nf = 0; nf < 8; ++nf) MMA_F16(d[mf][nf], a[mf], b[nf]);
    }
}

// stage this thread's accumulator rows belonging to 64-row half into sC64 [64][132]
__device__ __forceinline__ void stage_half(float* sC64, int m0w, int n0w, int lane,
                                           float d[2][8][4], int half) {
    if ((m0w >> 6) != half) return;
    const int g4 = lane >> 2, t4 = lane & 3;
    const int mb = m0w - half * 64;
#pragma unroll
    for (int mf = 0; mf < 2; ++mf)
#pragma unroll
        for (int nf = 0; nf < 8; ++nf) {
            int row = mb + mf * 16 + g4;
            int col = n0w + nf * 8 + t4 * 2;
            *(float2*)(sC64 + row * 132 + col)       = make_float2(d[mf][nf][0], d[mf][nf][1]);
            *(float2*)(sC64 + (row + 8) * 132 + col) = make_float2(d[mf][nf][2], d[mf][nf][3]);
        }
}

#define ZERO_D(d) \
    { _Pragma("unroll") for (int i = 0; i < 2; i++) \
      _Pragma("unroll") for (int j = 0; j < 8; j++) \
      _Pragma("unroll") for (int q = 0; q < 4; q++) (d)[i][j][q] = 0.0f; }

// ---------------- agemm: A-resident GEMM (K=128), loops ny col-groups --------
// smem: A [0,32K) resident; B double-buffer [32K,64K); sC64 overlay [32K,+33.8K)
// epi: 1 bias+relu fp16, 3 plain fp16
__global__ __launch_bounds__(256, 2)
void agemm(const __half* __restrict__ A,
           const __half* __restrict__ BT,
           int ny,
           __half* __restrict__ Ch, int Cstride,
           int epi, const float* __restrict__ bias)
{
    extern __shared__ uint32_t sm[];
    char* smc = (char*)sm;
    const uint32_t sbase = smem_u32(smc);
    float* sC64 = (float*)(smc + 32768);

    const int tid  = threadIdx.x;
    const int wid  = tid >> 5;
    const int lane = tid & 31;
    const int m0   = blockIdx.x * 128;
    const int m0w  = (wid >> 1) * 32;
    const int n0w  = (wid & 1) * 64;
    const int srow = tid >> 3, schk = tid & 7;

    // stage A (both chunks, resident)
#pragma unroll
    for (int ch = 0; ch < 2; ++ch) {
#pragma unroll
        for (int p = 0; p < 4; ++p) {
            int row = srow + p * 32;
            int ar  = m0 + row; if (ar >= NN) ar = NN - 1;
            uint32_t off = (uint32_t)row * 128u + (uint32_t)((schk ^ (row & 7)) << 4);
            cpa16(sbase + ch * 16384u + off, A + (size_t)ar * 128 + ch * 64 + schk * 8);
        }
        asm volatile("cp.async.commit_group;" ::: "memory");
    }

    for (int cy = 0; cy < ny; ++cy) {
        const int cg0 = cy * 128;
        __syncthreads();   // sC64 reads from previous cy done before B restage
#pragma unroll
        for (int ch = 0; ch < 2; ++ch) {
#pragma unroll
            for (int p = 0; p < 4; ++p) {
                int row = srow + p * 32;
                uint32_t off = (uint32_t)row * 128u + (uint32_t)((schk ^ (row & 7)) << 4);
                cpa16(sbase + 32768u + ch * 16384u + off,
                      BT + (size_t)(cg0 + row) * 128 + ch * 64 + schk * 8);
            }
            asm volatile("cp.async.commit_group;" ::: "memory");
        }
        float d[2][8][4];
        ZERO_D(d);
        asm volatile("cp.async.wait_group 1;" ::: "memory");
        __syncthreads();
        chunk_mma(sbase, sbase + 32768u, m0w, n0w, lane, d);
        asm volatile("cp.async.wait_group 0;" ::: "memory");
        __syncthreads();
        chunk_mma(sbase + 16384u, sbase + 49152u, m0w, n0w, lane, d);

        // epilogue: 64-row halves
#pragma unroll
        for (int half = 0; half < 2; ++half) {
            __syncthreads();
            stage_half(sC64, m0w, n0w, lane, d, half);
            __syncthreads();
#pragma unroll
            for (int p = 0; p < 2; ++p) {
                int i   = tid + p * 256;
                int row = i >> 3;
                int q   = (i & 7) << 4;
                int gr  = m0 + half * 64 + row;
                if (gr >= NN) continue;
                __half hb[16];
#pragma unroll
                for (int h = 0; h < 4; ++h) {
                    int c = q + h * 4;
                    float4 v = *(const float4*)(sC64 + row * 132 + c);
                    if (epi == 1) {
                        int cg = cg0 + c;
                        v.x = fmaxf(v.x + bias[cg + 0], 0.f);
                        v.y = fmaxf(v.y + bias[cg + 1], 0.f);
                        v.z = fmaxf(v.z + bias[cg + 2], 0.f);
                        v.w = fmaxf(v.w + bias[cg + 3], 0.f);
                    }
                    hb[h*4+0] = __float2half_rn(v.x);
                    hb[h*4+1] = __float2half_rn(v.y);
                    hb[h*4+2] = __float2half_rn(v.z);
                    hb[h*4+3] = __float2half_rn(v.w);
                }
                __half* dst = Ch + (size_t)gr * Cstride + cg0 + q;
                *(uint4*)(dst)     = *(uint4*)(hb);
                *(uint4*)(dst + 8) = *(uint4*)(hb + 8);
            }
        }
    }
}

// ---------------- kv2: fused K+V with resident gathered A --------------------
__global__ __launch_bounds__(256, 2)
void kv2(const int* __restrict__ nbr)
{
    extern __shared__ uint32_t sm[];
    char* smc = (char*)sm;
    const uint32_t sbase = smem_u32(smc);
    float* sC64 = (float*)(smc + 32768);
    __shared__ int rowg[128];
    __shared__ float sden[20];

    const int tid  = threadIdx.x;
    const int wid  = tid >> 5;
    const int lane = tid & 31;
    const int z    = blockIdx.z;
    const int m0   = blockIdx.x * 128;
    const int m0w  = (wid >> 1) * 32;
    const int n0w  = (wid & 1) * 64;
    const int srow = tid >> 3, schk = tid & 7;

    if (tid < 128) {
        int gr  = m0 + tid;
        int idx = (gr < NN) ? gr : (NN - 1);
        if (z > 0 && gr < NN) idx = nbr[gr * 4 + (z - 1)];
        rowg[tid] = idx;
    }
    if (tid < 20) sden[tid] = 0.0f;
    __syncthreads();

    const __half* Bz = g_WKVh + (size_t)z * 32768;

    // stage A (resident) + B-K chunks; 4 commit groups
#pragma unroll
    for (int ch = 0; ch < 2; ++ch) {
#pragma unroll
        for (int p = 0; p < 4; ++p) {
            int row = srow + p * 32;
            uint32_t off = (uint32_t)row * 128u + (uint32_t)((schk ^ (row & 7)) << 4);
            cpa16(sbase + ch * 16384u + off,
                  g_Xh + (size_t)rowg[row] * 128 + ch * 64 + schk * 8);
        }
        asm volatile("cp.async.commit_group;" ::: "memory");
    }
#pragma unroll
    for (int ch = 0; ch < 2; ++ch) {
#pragma unroll
        for (int p = 0; p < 4; ++p) {
            int row = srow + p * 32;
            uint32_t off = (uint32_t)row * 128u + (uint32_t)((schk ^ (row & 7)) << 4);
            cpa16(sbase + 32768u + ch * 16384u + off,
                  Bz + (size_t)row * 128 + ch * 64 + schk * 8);
        }
        asm volatile("cp.async.commit_group;" ::: "memory");
    }

    float d[2][8][4];
    ZERO_D(d);
    asm volatile("cp.async.wait_group 1;" ::: "memory");
    __syncthreads();
    chunk_mma(sbase, sbase + 32768u, m0w, n0w, lane, d);
    asm volatile("cp.async.wait_group 0;" ::: "memory");
    __syncthreads();
    chunk_mma(sbase + 16384u, sbase + 49152u, m0w, n0w, lane, d);

    // ---- K epilogue: fused logits + denominators, 64-row halves ----
    const float scale = 0.1767766952966369f;   // 1/sqrt(32)
    float esum[4] = {0.f, 0.f, 0.f, 0.f};
#pragma unroll
    for (int half = 0; half < 2; ++half) {
        __syncthreads();
        stage_half(sC64, m0w, n0w, lane, d, half);
        __syncthreads();
        for (int rr = wid; rr < 64; rr += 8) {
            int gr = m0 + half * 64 + rr;
            if (gr >= NN) continue;
            const __half* qp = g_Qh + (size_t)gr * 128;
#pragma unroll
            for (int h = 0; h < 4; ++h) {
                float s = sC64[rr * 132 + h * 32 + lane] * __half2float(qp[h * 32 + lane]);
#pragma unroll
                for (int o = 16; o > 0; o >>= 1) s += __shfl_xor_sync(0xffffffffu, s, o);
                if (lane == 0) {
                    float e = expf(s * scale);
                    g_E[(size_t)gr * 20 + h * 5 + z] = e;
                    esum[h] += e;
                }
            }
        }
    }
    if (lane == 0) {
#pragma unroll
        for (int h = 0; h < 4; ++h) atomicAdd(&sden[h * 5 + z], esum[h]);
    }
    __syncthreads();
    if (tid < 20 && sden[tid] != 0.0f) atomicAdd(&g_denom[tid], sden[tid]);
    __syncthreads();

    // ---- stage B-V (A still resident), compute V ----
#pragma unroll
    for (int ch = 0; ch < 2; ++ch) {
#pragma unroll
        for (int p = 0; p < 4; ++p) {
            int row = srow + p * 32;
            uint32_t off = (uint32_t)row * 128u + (uint32_t)((schk ^ (row & 7)) << 4);
            cpa16(sbase + 32768u + ch * 16384u + off,
                  Bz + (size_t)(128 + row) * 128 + ch * 64 + schk * 8);
        }
        asm volatile("cp.async.commit_group;" ::: "memory");
    }
    ZERO_D(d);
    asm volatile("cp.async.wait_group 1;" ::: "memory");
    __syncthreads();
    chunk_mma(sbase, sbase + 32768u, m0w, n0w, lane, d);
    asm volatile("cp.async.wait_group 0;" ::: "memory");
    __syncthreads();
    chunk_mma(sbase + 16384u, sbase + 49152u, m0w, n0w, lane, d);

    // ---- V epilogue: fp16 store, 64-row halves ----
#pragma unroll
    for (int half = 0; half < 2; ++half) {
        __syncthreads();
        stage_half(sC64, m0w, n0w, lane, d, half);
        __syncthreads();
#pragma unroll
        for (int p = 0; p < 2; ++p) {
            int i   = tid + p * 256;
            int row = i >> 3;
            int q   = (i & 7) << 4;
            int gr  = m0 + half * 64 + row;
            if (gr >= NN) continue;
            __half hb[16];
#pragma unroll
            for (int h = 0; h < 4; ++h) {
                int c = q + h * 4;
                float4 v = *(const float4*)(sC64 + row * 132 + c);
                hb[h*4+0] = __float2half_rn(v.x);
                hb[h*4+1] = __float2half_rn(v.y);
                hb[h*4+2] = __float2half_rn(v.z);
                hb[h*4+3] = __float2half_rn(v.w);
            }
            __half* dst = g_Vh + ((size_t)z * NN + gr) * 128 + q;
            *(uint4*)(dst)     = *(uint4*)(hb);
            *(uint4*)(dst + 8) = *(uint4*)(hb + 8);
        }
    }
}

// ---------------- FFN2 GEMM (K=512) + resid + LN2, classic double-buffer -----
__global__ __launch_bounds__(256, 2)
void tgemm2(const __half* __restrict__ A,
            const __half* __restrict__ BT,
            float* __restrict__ C,
            const float* __restrict__ bias,
            const float* __restrict__ resid,
            const float* __restrict__ gamma,
            const float* __restrict__ beta)
{
    extern __shared__ uint32_t sm[];
    char* smc = (char*)sm;
    const uint32_t sbase = smem_u32(smc);

    const int tid  = threadIdx.x;
    const int wid  = tid >> 5;
    const int lane = tid & 31;
    const int m0   = blockIdx.x * 128;
    const int m0w  = (wid >> 1) * 32;
    const int n0w  = (wid & 1) * 64;
    const int srow = tid >> 3, schk = tid & 7;

    float d[2][8][4];
    ZERO_D(d);

    auto stage = [&](int bsel, int kc) {
        const int kg0 = kc * 64;
        uint32_t abase = sbase + (uint32_t)bsel * 16384u;
        uint32_t bbase = sbase + 32768u + (uint32_t)bsel * 16384u;
#pragma unroll
        for (int p = 0; p < 4; ++p) {
            int row = srow + p * 32;
            int ar  = m0 + row; if (ar >= NN) ar = NN - 1;
            uint32_t off = (uint32_t)row * 128u + (uint32_t)((schk ^ (row & 7)) << 4);
            cpa16(abase + off, A + (size_t)ar * 512 + kg0 + schk * 8);
            cpa16(bbase + off, BT + (size_t)row * 512 + kg0 + schk * 8);
        }
        asm volatile("cp.async.commit_group;" ::: "memory");
    };

    stage(0, 0);
    for (int kc = 0; kc < 8; ++kc) {
        const int bsel = kc & 1;
        if (kc + 1 < 8) { stage(bsel ^ 1, kc + 1);
            asm volatile("cp.async.wait_group 1;" ::: "memory");
        } else { asm volatile("cp.async.wait_group 0;" ::: "memory"); }
        __syncthreads();
        chunk_mma(sbase + (uint32_t)bsel * 16384u,
                  sbase + 32768u + (uint32_t)bsel * 16384u, m0w, n0w, lane, d);
        __syncthreads();
    }

    float* sC = (float*)sm;
    const int g4 = lane >> 2, t4 = lane & 3;
#pragma unroll
    for (int mf = 0; mf < 2; ++mf)
#pragma unroll
        for (int nf = 0; nf < 8; ++nf) {
            int row = m0w + mf * 16 + g4;
            int col = n0w + nf * 8 + t4 * 2;
            *(float2*)(sC + row * 132 + col)       = make_float2(d[mf][nf][0], d[mf][nf][1]);
            *(float2*)(sC + (row + 8) * 132 + col) = make_float2(d[mf][nf][2], d[mf][nf][3]);
        }
    __syncthreads();

    for (int rr = wid; rr < 128; rr += 8) {
        int gr = m0 + rr;
        if (gr >= NN) continue;
        const float* rp = resid + (size_t)gr * 128;
        float v0 = sC[rr * 132 + lane]      + bias[lane]      + rp[lane];
        float v1 = sC[rr * 132 + 32 + lane] + bias[32 + lane] + rp[32 + lane];
        float v2 = sC[rr * 132 + 64 + lane] + bias[64 + lane] + rp[64 + lane];
        float v3 = sC[rr * 132 + 96 + lane] + bias[96 + lane] + rp[96 + lane];
        float s1 = v0 + v1 + v2 + v3;
        float s2 = v0 * v0 + v1 * v1 + v2 * v2 + v3 * v3;
#pragma unroll
        for (int o = 16; o > 0; o >>= 1) {
            s1 += __shfl_xor_sync(0xffffffffu, s1, o);
            s2 += __shfl_xor_sync(0xffffffffu, s2, o);
        }
        float mu  = s1 * (1.0f / 128.0f);
        float var = s2 * (1.0f / 128.0f) - mu * mu;
        float rs  = rsqrtf(var + 1e-5f);
        float* dst = C + (size_t)gr * 128;
        dst[lane]      = (v0 - mu) * rs * gamma[lane]      + beta[lane];
        dst[lane + 32] = (v1 - mu) * rs * gamma[lane + 32] + beta[lane + 32];
        dst[lane + 64] = (v2 - mu) * rs * gamma[lane + 64] + beta[lane + 64];
        dst[lane + 96] = (v3 - mu) * rs * gamma[lane + 96] + beta[lane + 96];
    }
}

// ---------------- combine + residual + LN1 ----------------
__global__ void combine_ln1_kernel(const float* __restrict__ x,
                                   const float* __restrict__ g1,
                                   const float* __restrict__ be1) {
    __shared__ float sinv[20];
    const int tid = threadIdx.x;
    if (tid < 20) sinv[tid] = 1.0f / g_denom[tid];
    __syncthreads();
    const int n    = blockIdx.x * 8 + (tid >> 5);
    const int lane = tid & 31;
    if (n >= NN) return;
    float t[4];
    float s1 = 0.0f, s2 = 0.0f;
#pragma unroll
    for (int h = 0; h < 4; h++) {
        float z = 0.0f;
#pragma unroll
        for (int r = 0; r < 5; r++) {
            float p = g_E[(size_t)n * 20 + h * 5 + r] * sinv[h * 5 + r];
            z = fmaf(p, __half2float(g_Vh[((size_t)r * NN + n) * 128 + h * 32 + lane]), z);
        }
        float v = x[(size_t)n * 128 + h * 32 + lane] + z;
        t[h] = v;
        s1 += v;
        s2 = fmaf(v, v, s2);
    }
#pragma unroll
    for (int o = 16; o > 0; o >>= 1) {
        s1 += __shfl_xor_sync(0xffffffffu, s1, o);
        s2 += __shfl_xor_sync(0xffffffffu, s2, o);
    }
    float mu  = s1 * (1.0f / 128.0f);
    float var = s2 * (1.0f / 128.0f) - mu * mu;
    float rs  = rsqrtf(var + 1e-5f);
#pragma unroll
    for (int h = 0; h < 4; h++) {
        int c = h * 32 + lane;
        float hv = (t[h] - mu) * rs * g1[c] + be1[c];
        g_H  [(size_t)n * 128 + c] = hv;
        g_Hth[(size_t)n * 128 + c] = __float2half_rn(hv);
    }
}

// ---------------- launch ----------------
extern "C" void kernel_launch(void* const* d_in, const int* in_sizes, int n_in,
                              void* d_out, int out_size)
{
    const float* x   = (const float*)d_in[0];
    const int*   nbr = (const int*)  d_in[1];
    const float* wq  = (const float*)d_in[2];
    const float* wk  = (const float*)d_in[3];
    const float* wv  = (const float*)d_in[4];
    const float* W1  = (const float*)d_in[5];
    const float* b1  = (const float*)d_in[6];
    const float* W2  = (const float*)d_in[7];
    const float* b2  = (const float*)d_in[8];
    const float* g1  = (const float*)d_in[9];
    const float* be1 = (const float*)d_in[10];
    const float* g2  = (const float*)d_in[11];
    const float* be2 = (const float*)d_in[12];
    float* out = (float*)d_out;

    void *pXh, *pQh, *pH, *pHth, *pFh, *pWQ, *pW1, *pW2;
    cudaGetSymbolAddress(&pXh, g_Xh);
    cudaGetSymbolAddress(&pQh, g_Qh);
    cudaGetSymbolAddress(&pH,  g_H);
    cudaGetSymbolAddress(&pHth, g_Hth);
    cudaGetSymbolAddress(&pFh, g_Fh);
    cudaGetSymbolAddress(&pWQ, g_WQh);
    cudaGetSymbolAddress(&pW1, g_W1h);
    cudaGetSymbolAddress(&pW2, g_W2h);

    const size_t SMEM_AG = 32768 + (size_t)64 * 132 * sizeof(float);   // 66560
    const size_t SMEM_T2 = (size_t)128 * 132 * sizeof(float);          // 67584
    cudaFuncSetAttribute((const void*)agemm,
                         cudaFuncAttributeMaxDynamicSharedMemorySize, (int)SMEM_AG);
    cudaFuncSetAttribute((const void*)kv2,
                         cudaFuncAttributeMaxDynamicSharedMemorySize, (int)SMEM_AG);
    cudaFuncSetAttribute((const void*)tgemm2,
                         cudaFuncAttributeMaxDynamicSharedMemorySize, (int)SMEM_T2);

    const int GN = (NN + 127) / 128;   // 782

    conv_x_kernel<<<12500, 256>>>(x);                                      // 1
    trans_all<<<1216, 256>>>(wk, wv, wq, W1, W2);                          // 2

    // 3: Q = Xh @ Wq -> g_Qh (fp16)
    agemm<<<GN, 256, SMEM_AG>>>(
        (const __half*)pXh, (const __half*)pWQ, 1,
        (__half*)pQh, 128, 3, nullptr);

    // 4: fused K+V GEMM + logits + denoms + V store
    kv2<<<dim3(GN, 1, 5), 256, SMEM_AG>>>(nbr);

    // 5: combine + residual + LN1
    combine_ln1_kernel<<<NN / 8, 256>>>(x, g1, be1);

    // 6: FFN1: relu(Hth @ W1 + b1) -> g_Fh (fp16), 4 col-groups per CTA
    agemm<<<GN, 256, SMEM_AG>>>(
        (const __half*)pHth, (const __half*)pW1, 4,
        (__half*)pFh, 512, 1, b1);

    // 7: FFN2 + resid(H exact) + LN2 -> out
    tgemm2<<<GN, 256, SMEM_T2>>>(
        (const __half*)pFh, (const __half*)pW2,
        out, b2, (const float*)pH, g2, be2);
}

// round 13
// speedup vs baseline: 1.5386x; 1.4652x over previous
#include <cuda_runtime.h>
#include <cuda_fp16.h>
#include <cstdint>
#include <math.h>

#define NN 100000

// ---------------- scratch ----------------
__device__ __half g_Xh [(size_t)NN * 128];
__device__ __half g_Qh [(size_t)NN * 128];
__device__ __half g_Vh [(size_t)5 * NN * 128];
__device__ float  g_E  [(size_t)NN * 20];
__device__ float  g_H  [(size_t)NN * 128];
__device__ __half g_Hth[(size_t)NN * 128];
__device__ __half g_Fh [(size_t)NN * 512];
__device__ __half g_WQh [128 * 128];
__device__ __half g_WKVh[5 * 256 * 128];   // [r][c(K:0-127,V:128-255)][k]
__device__ __half g_W1h [512 * 128];
__device__ __half g_W2h [128 * 512];
__device__ float  g_denom[20];

__device__ __forceinline__ uint32_t smem_u32(const void* p) {
    uint32_t a;
    asm("{ .reg .u64 t; cvta.to.shared.u64 t, %1; cvt.u32.u64 %0, t; }" : "=r"(a) : "l"(p));
    return a;
}
__device__ __forceinline__ void cpa16(uint32_t dst, const void* src) {
    asm volatile("cp.async.ca.shared.global [%0], [%1], 16;" :: "r"(dst), "l"(src));
}

__global__ void conv_x_kernel(const float* __restrict__ x) {
    if (blockIdx.x == 0 && threadIdx.x < 20) g_denom[threadIdx.x] = 0.0f;
    size_t i = ((size_t)blockIdx.x * 256 + threadIdx.x) * 4;
    if (i >= (size_t)NN * 128) return;
    float4 v = *(const float4*)(x + i);
    *(__half2*)(g_Xh + i)     = __floats2half2_rn(v.x, v.y);
    *(__half2*)(g_Xh + i + 2) = __floats2half2_rn(v.z, v.w);
}

__global__ void trans_all(const float* __restrict__ wk, const float* __restrict__ wv,
                          const float* __restrict__ wq, const float* __restrict__ W1,
                          const float* __restrict__ W2) {
    int b = blockIdx.x;
    int tid = threadIdx.x;
    if (b < 640) {
        int z = b >> 7;
        int idx = (b & 127) * 256 + tid;
        int c = idx >> 7, k = idx & 127;
        float v;
        if (c < 128) {
            v = wk[(size_t)(c >> 5) * 20480 + (size_t)z * 4096 + k * 32 + (c & 31)];
        } else {
            int c2 = c - 128;
            v = wv[(size_t)(c2 >> 5) * 20480 + (size_t)z * 4096 + k * 32 + (c2 & 31)];
        }
        g_WKVh[(size_t)z * 32768 + idx] = __float2half_rn(v);
    } else {
        int b2 = b - 640;
        if (b2 < 64) {
            int idx = b2 * 256 + tid;
            int c = idx >> 7, k = idx & 127;
            g_WQh[idx] = __float2half_rn(wq[(size_t)(c >> 5) * 4096 + k * 32 + (c & 31)]);
        } else if (b2 < 320) {
            int idx = (b2 - 64) * 256 + tid;
            int c = idx >> 7, k = idx & 127;
            g_W1h[idx] = __float2half_rn(W1[(size_t)k * 512 + c]);
        } else {
            int idx = (b2 - 320) * 256 + tid;
            int c = idx >> 9, k = idx & 511;
            g_W2h[idx] = __float2half_rn(W2[(size_t)k * 128 + c]);
        }
    }
}

#define LDM_X4(r0,r1,r2,r3,addr) \
    asm volatile("ldmatrix.sync.aligned.m8n8.x4.shared.b16 {%0,%1,%2,%3}, [%4];" \
                 : "=r"(r0), "=r"(r1), "=r"(r2), "=r"(r3) : "r"(addr))
#define MMA_F16(dd,aa,bb) \
    asm volatile("mma.sync.aligned.m16n8k16.row.col.f32.f16.f16.f32 " \
                 "{%0,%1,%2,%3}, {%4,%5,%6,%7}, {%8,%9}, {%0,%1,%2,%3};" \
                 : "+f"((dd)[0]), "+f"((dd)[1]), "+f"((dd)[2]), "+f"((dd)[3]) \
                 : "r"((aa)[0]), "r"((aa)[1]), "r"((aa)[2]), "r"((aa)[3]), \
                   "r"((bb)[0]), "r"((bb)[1]))

__device__ __forceinline__ void chunk_mma(uint32_t abase, uint32_t bbase,
                                          int m0w, int n0w, int lane,
                                          float d[2][8][4]) {
    const int lrow = lane & 7;
    const int a_hi = (lane >> 3) >> 1, a_roff = ((lane >> 3) & 1) * 8;
    const int b_hi = (lane >> 3) & 1,  b_coff = (lane >> 4) * 8;
#pragma unroll
    for (int ks = 0; ks < 4; ++ks) {
        uint32_t a[2][4], b[8][2];
#pragma unroll
        for (int mf = 0; mf < 2; ++mf) {
            int r = m0w + mf * 16 + lrow + a_roff;
            uint32_t addr = abase + (uint32_t)r * 128u
                          + (uint32_t)(((2 * ks + a_hi) ^ lrow) << 4);
            LDM_X4(a[mf][0], a[mf][1], a[mf][2], a[mf][3], addr);
        }
#pragma unroll
        for (int pr = 0; pr < 4; ++pr) {
            int c = n0w + pr * 16 + lrow + b_coff;
            uint32_t addr = bbase + (uint32_t)c * 128u
                          + (uint32_t)(((2 * ks + b_hi) ^ (c & 7)) << 4);
            LDM_X4(b[2*pr][0], b[2*pr][1], b[2*pr+1][0], b[2*pr+1][1], addr);
        }
#pragma unroll
        for (int mf = 0; mf < 2; ++mf)
#pragma unroll
            for (int nf = 0; nf < 8; ++nf) MMA_F16(d[mf][nf], a[mf], b[nf]);
    }
}

__device__ __forceinline__ void stage_half(float* sC64, int m0w, int n0w, int lane,
                                           float d[2][8][4], int half) {
    if ((m0w >> 6) != half) return;
    const int g4 = lane >> 2, t4 = lane & 3;
    const int mb = m0w - half * 64;
#pragma unroll
    for (int mf = 0; mf < 2; ++mf)
#pragma unroll
        for (int nf = 0; nf < 8; ++nf) {
            int row = mb + mf * 16 + g4;
            int col = n0w + nf * 8 + t4 * 2;
            *(float2*)(sC64 + row * 132 + col)       = make_float2(d[mf][nf][0], d[mf][nf][1]);
            *(float2*)(sC64 + (row + 8) * 132 + col) = make_float2(d[mf][nf][2], d[mf][nf][3]);
        }
}

#define ZERO_D(d) \
    { _Pragma("unroll") for (int i = 0; i < 2; i++) \
      _Pragma("unroll") for (int j = 0; j < 8; j++) \
      _Pragma("unroll") for (int q = 0; q < 4; q++) (d)[i][j][q] = 0.0f; }

// ---------------- agemm: A-resident GEMM (K=128), loops ny col-groups --------
__global__ __launch_bounds__(256, 2)
void agemm(const __half* __restrict__ A,
           const __half* __restrict__ BT,
           int ny,
           __half* __restrict__ Ch, int Cstride,
           int epi, const float* __restrict__ bias)
{
    extern __shared__ uint32_t sm[];
    char* smc = (char*)sm;
    const uint32_t sbase = smem_u32(smc);
    float* sC64 = (float*)(smc + 32768);

    const int tid  = threadIdx.x;
    const int wid  = tid >> 5;
    const int lane = tid & 31;
    const int m0   = blockIdx.x * 128;
    const int m0w  = (wid >> 1) * 32;
    const int n0w  = (wid & 1) * 64;
    const int srow = tid >> 3, schk = tid & 7;

#pragma unroll
    for (int ch = 0; ch < 2; ++ch) {
#pragma unroll
        for (int p = 0; p < 4; ++p) {
            int row = srow + p * 32;
            int ar  = m0 + row; if (ar >= NN) ar = NN - 1;
            uint32_t off = (uint32_t)row * 128u + (uint32_t)((schk ^ (row & 7)) << 4);
            cpa16(sbase + ch * 16384u + off, A + (size_t)ar * 128 + ch * 64 + schk * 8);
        }
        asm volatile("cp.async.commit_group;" ::: "memory");
    }

    for (int cy = 0; cy < ny; ++cy) {
        const int cg0 = cy * 128;
        __syncthreads();
#pragma unroll
        for (int ch = 0; ch < 2; ++ch) {
#pragma unroll
            for (int p = 0; p < 4; ++p) {
                int row = srow + p * 32;
                uint32_t off = (uint32_t)row * 128u + (uint32_t)((schk ^ (row & 7)) << 4);
                cpa16(sbase + 32768u + ch * 16384u + off,
                      BT + (size_t)(cg0 + row) * 128 + ch * 64 + schk * 8);
            }
            asm volatile("cp.async.commit_group;" ::: "memory");
        }
        float d[2][8][4];
        ZERO_D(d);
        asm volatile("cp.async.wait_group 1;" ::: "memory");
        __syncthreads();
        chunk_mma(sbase, sbase + 32768u, m0w, n0w, lane, d);
        asm volatile("cp.async.wait_group 0;" ::: "memory");
        __syncthreads();
        chunk_mma(sbase + 16384u, sbase + 49152u, m0w, n0w, lane, d);

#pragma unroll
        for (int half = 0; half < 2; ++half) {
            __syncthreads();
            stage_half(sC64, m0w, n0w, lane, d, half);
            __syncthreads();
#pragma unroll
            for (int p = 0; p < 2; ++p) {
                int i   = tid + p * 256;
                int row = i >> 3;
                int q   = (i & 7) << 4;
                int gr  = m0 + half * 64 + row;
                if (gr >= NN) continue;
                __half hb[16];
#pragma unroll
                for (int h = 0; h < 4; ++h) {
                    int c = q + h * 4;
                    float4 v = *(const float4*)(sC64 + row * 132 + c);
                    if (epi == 1) {
                        int cg = cg0 + c;
                        v.x = fmaxf(v.x + bias[cg + 0], 0.f);
                        v.y = fmaxf(v.y + bias[cg + 1], 0.f);
                        v.z = fmaxf(v.z + bias[cg + 2], 0.f);
                        v.w = fmaxf(v.w + bias[cg + 3], 0.f);
                    }
                    hb[h*4+0] = __float2half_rn(v.x);
                    hb[h*4+1] = __float2half_rn(v.y);
                    hb[h*4+2] = __float2half_rn(v.z);
                    hb[h*4+3] = __float2half_rn(v.w);
                }
                __half* dst = Ch + (size_t)gr * Cstride + cg0 + q;
                *(uint4*)(dst)     = *(uint4*)(hb);
                *(uint4*)(dst + 8) = *(uint4*)(hb + 8);
            }
        }
    }
}

// ---------------- kv2: fused K+V, register logits epilogue, B-V prefetch -----
__global__ __launch_bounds__(256, 2)
void kv2(const int* __restrict__ nbr)
{
    extern __shared__ uint32_t sm[];
    char* smc = (char*)sm;
    const uint32_t sbase = smem_u32(smc);
    float* sC64 = (float*)(smc + 32768);
    __shared__ int rowg[128];
    __shared__ float sden[20];

    const int tid  = threadIdx.x;
    const int wid  = tid >> 5;
    const int lane = tid & 31;
    const int g4   = lane >> 2, t4 = lane & 3;
    const int z    = blockIdx.z;
    const int m0   = blockIdx.x * 128;
    const int m0w  = (wid >> 1) * 32;
    const int n0w  = (wid & 1) * 64;
    const int srow = tid >> 3, schk = tid & 7;

    if (tid < 128) {
        int gr  = m0 + tid;
        int idx = (gr < NN) ? gr : (NN - 1);
        if (z > 0 && gr < NN) idx = nbr[gr * 4 + (z - 1)];
        rowg[tid] = idx;
    }
    if (tid < 20) sden[tid] = 0.0f;
    __syncthreads();

    const __half* Bz = g_WKVh + (size_t)z * 32768;

    // stage A (resident) and B-K
#pragma unroll
    for (int ch = 0; ch < 2; ++ch) {
#pragma unroll
        for (int p = 0; p < 4; ++p) {
            int row = srow + p * 32;
            uint32_t off = (uint32_t)row * 128u + (uint32_t)((schk ^ (row & 7)) << 4);
            cpa16(sbase + ch * 16384u + off,
                  g_Xh + (size_t)rowg[row] * 128 + ch * 64 + schk * 8);
        }
        asm volatile("cp.async.commit_group;" ::: "memory");
    }
#pragma unroll
    for (int ch = 0; ch < 2; ++ch) {
#pragma unroll
        for (int p = 0; p < 4; ++p) {
            int row = srow + p * 32;
            uint32_t off = (uint32_t)row * 128u + (uint32_t)((schk ^ (row & 7)) << 4);
            cpa16(sbase + 32768u + ch * 16384u + off,
                  Bz + (size_t)row * 128 + ch * 64 + schk * 8);
        }
        asm volatile("cp.async.commit_group;" ::: "memory");
    }

    float d[2][8][4];
    ZERO_D(d);
    asm volatile("cp.async.wait_group 1;" ::: "memory");
    __syncthreads();
    chunk_mma(sbase, sbase + 32768u, m0w, n0w, lane, d);
    asm volatile("cp.async.wait_group 0;" ::: "memory");
    __syncthreads();
    chunk_mma(sbase + 16384u, sbase + 49152u, m0w, n0w, lane, d);
    __syncthreads();   // all warps done reading B-K buffers

    // ---- prefetch B-V into the (now free) B buffers ----
#pragma unroll
    for (int ch = 0; ch < 2; ++ch) {
#pragma unroll
        for (int p = 0; p < 4; ++p) {
            int row = srow + p * 32;
            uint32_t off = (uint32_t)row * 128u + (uint32_t)((schk ^ (row & 7)) << 4);
            cpa16(sbase + 32768u + ch * 16384u + off,
                  Bz + (size_t)(128 + row) * 128 + ch * 64 + schk * 8);
        }
        asm volatile("cp.async.commit_group;" ::: "memory");
    }

    // ---- register-resident logits epilogue (overlaps B-V loads) ----
    // warp owns full heads: n0w=0 -> heads 0,1 ; n0w=64 -> heads 2,3
    {
        const float scale = 0.1767766952966369f;   // 1/sqrt(32)
        const int hbase = n0w >> 5;
        float esum0 = 0.f, esum1 = 0.f;
#pragma unroll
        for (int mf = 0; mf < 2; ++mf)
#pragma unroll
            for (int rh = 0; rh < 2; ++rh) {
                int gr = m0 + m0w + mf * 16 + g4 + rh * 8;
                bool valid = gr < NN;
                const __half2* qp = (const __half2*)(g_Qh + (size_t)(valid ? gr : 0) * 128);
#pragma unroll
                for (int hg = 0; hg < 2; ++hg) {
                    float s = 0.f;
#pragma unroll
                    for (int j = 0; j < 4; ++j) {
                        int nf = hg * 4 + j;
                        int col0 = n0w + nf * 8 + t4 * 2;
                        float2 qv = __half22float2(qp[col0 >> 1]);
                        s = fmaf(d[mf][nf][2*rh],     qv.x, s);
                        s = fmaf(d[mf][nf][2*rh + 1], qv.y, s);
                    }
                    s += __shfl_xor_sync(0xffffffffu, s, 1);
                    s += __shfl_xor_sync(0xffffffffu, s, 2);
                    if (t4 == 0 && valid) {
                        float e = expf(s * scale);
                        g_E[(size_t)gr * 20 + (hbase + hg) * 5 + z] = e;
                        if (hg == 0) esum0 += e; else esum1 += e;
                    }
                }
            }
        if (t4 == 0) {
            atomicAdd(&sden[(hbase + 0) * 5 + z], esum0);
            atomicAdd(&sden[(hbase + 1) * 5 + z], esum1);
        }
    }
    __syncthreads();
    if (tid < 20 && sden[tid] != 0.0f) atomicAdd(&g_denom[tid], sden[tid]);

    // ---- V mainloop (A resident, B-V prefetched) ----
    ZERO_D(d);
    asm volatile("cp.async.wait_group 1;" ::: "memory");
    __syncthreads();
    chunk_mma(sbase, sbase + 32768u, m0w, n0w, lane, d);
    asm volatile("cp.async.wait_group 0;" ::: "memory");
    __syncthreads();
    chunk_mma(sbase + 16384u, sbase + 49152u, m0w, n0w, lane, d);

    // ---- V epilogue: fp16 store via 64-row halves ----
#pragma unroll
    for (int half = 0; half < 2; ++half) {
        __syncthreads();
        stage_half(sC64, m0w, n0w, lane, d, half);
        __syncthreads();
#pragma unroll
        for (int p = 0; p < 2; ++p) {
            int i   = tid + p * 256;
            int row = i >> 3;
            int q   = (i & 7) << 4;
            int gr  = m0 + half * 64 + row;
            if (gr >= NN) continue;
            __half hb[16];
#pragma unroll
            for (int h = 0; h < 4; ++h) {
                int c = q + h * 4;
                float4 v = *(const float4*)(sC64 + row * 132 + c);
                hb[h*4+0] = __float2half_rn(v.x);
                hb[h*4+1] = __float2half_rn(v.y);
                hb[h*4+2] = __float2half_rn(v.z);
                hb[h*4+3] = __float2half_rn(v.w);
            }
            __half* dst = g_Vh + ((size_t)z * NN + gr) * 128 + q;
            *(uint4*)(dst)     = *(uint4*)(hb);
            *(uint4*)(dst + 8) = *(uint4*)(hb + 8);
        }
    }
}

// ---------------- FFN2 GEMM (K=512) + resid + LN2 ----------------
__global__ __launch_bounds__(256, 2)
void tgemm2(const __half* __restrict__ A,
            const __half* __restrict__ BT,
            float* __restrict__ C,
            const float* __restrict__ bias,
            const float* __restrict__ resid,
            const float* __restrict__ gamma,
            const float* __restrict__ beta)
{
    extern __shared__ uint32_t sm[];
    char* smc = (char*)sm;
    const uint32_t sbase = smem_u32(smc);

    const int tid  = threadIdx.x;
    const int wid  = tid >> 5;
    const int lane = tid & 31;
    const int m0   = blockIdx.x * 128;
    const int m0w  = (wid >> 1) * 32;
    const int n0w  = (wid & 1) * 64;
    const int srow = tid >> 3, schk = tid & 7;

    float d[2][8][4];
    ZERO_D(d);

    auto stage = [&](int bsel, int kc) {
        const int kg0 = kc * 64;
        uint32_t abase = sbase + (uint32_t)bsel * 16384u;
        uint32_t bbase = sbase + 32768u + (uint32_t)bsel * 16384u;
#pragma unroll
        for (int p = 0; p < 4; ++p) {
            int row = srow + p * 32;
            int ar  = m0 + row; if (ar >= NN) ar = NN - 1;
            uint32_t off = (uint32_t)row * 128u + (uint32_t)((schk ^ (row & 7)) << 4);
            cpa16(abase + off, A + (size_t)ar * 512 + kg0 + schk * 8);
            cpa16(bbase + off, BT + (size_t)row * 512 + kg0 + schk * 8);
        }
        asm volatile("cp.async.commit_group;" ::: "memory");
    };

    stage(0, 0);
    for (int kc = 0; kc < 8; ++kc) {
        const int bsel = kc & 1;
        if (kc + 1 < 8) { stage(bsel ^ 1, kc + 1);
            asm volatile("cp.async.wait_group 1;" ::: "memory");
        } else { asm volatile("cp.async.wait_group 0;" ::: "memory"); }
        __syncthreads();
        chunk_mma(sbase + (uint32_t)bsel * 16384u,
                  sbase + 32768u + (uint32_t)bsel * 16384u, m0w, n0w, lane, d);
        __syncthreads();
    }

    float* sC = (float*)sm;
    const int g4 = lane >> 2, t4 = lane & 3;
#pragma unroll
    for (int mf = 0; mf < 2; ++mf)
#pragma unroll
        for (int nf = 0; nf < 8; ++nf) {
            int row = m0w + mf * 16 + g4;
            int col = n0w + nf * 8 + t4 * 2;
            *(float2*)(sC + row * 132 + col)       = make_float2(d[mf][nf][0], d[mf][nf][1]);
            *(float2*)(sC + (row + 8) * 132 + col) = make_float2(d[mf][nf][2], d[mf][nf][3]);
        }
    __syncthreads();

    for (int rr = wid; rr < 128; rr += 8) {
        int gr = m0 + rr;
        if (gr >= NN) continue;
        const float* rp = resid + (size_t)gr * 128;
        float v0 = sC[rr * 132 + lane]      + bias[lane]      + rp[lane];
        float v1 = sC[rr * 132 + 32 + lane] + bias[32 + lane] + rp[32 + lane];
        float v2 = sC[rr * 132 + 64 + lane] + bias[64 + lane] + rp[64 + lane];
        float v3 = sC[rr * 132 + 96 + lane] + bias[96 + lane] + rp[96 + lane];
        float s1 = v0 + v1 + v2 + v3;
        float s2 = v0 * v0 + v1 * v1 + v2 * v2 + v3 * v3;
#pragma unroll
        for (int o = 16; o > 0; o >>= 1) {
            s1 += __shfl_xor_sync(0xffffffffu, s1, o);
            s2 += __shfl_xor_sync(0xffffffffu, s2, o);
        }
        float mu  = s1 * (1.0f / 128.0f);
        float var = s2 * (1.0f / 128.0f) - mu * mu;
        float rs  = rsqrtf(var + 1e-5f);
        float* dst = C + (size_t)gr * 128;
        dst[lane]      = (v0 - mu) * rs * gamma[lane]      + beta[lane];
        dst[lane + 32] = (v1 - mu) * rs * gamma[lane + 32] + beta[lane + 32];
        dst[lane + 64] = (v2 - mu) * rs * gamma[lane + 64] + beta[lane + 64];
        dst[lane + 96] = (v3 - mu) * rs * gamma[lane + 96] + beta[lane + 96];
    }
}

// ---------------- combine + residual + LN1 ----------------
__global__ void combine_ln1_kernel(const float* __restrict__ x,
                                   const float* __restrict__ g1,
                                   const float* __restrict__ be1) {
    __shared__ float sinv[20];
    const int tid = threadIdx.x;
    if (tid < 20) sinv[tid] = 1.0f / g_denom[tid];
    __syncthreads();
    const int n    = blockIdx.x * 8 + (tid >> 5);
    const int lane = tid & 31;
    if (n >= NN) return;
    float t[4];
    float s1 = 0.0f, s2 = 0.0f;
#pragma unroll
    for (int h = 0; h < 4; h++) {
        float z = 0.0f;
#pragma unroll
        for (int r = 0; r < 5; r++) {
            float p = g_E[(size_t)n * 20 + h * 5 + r] * sinv[h * 5 + r];
            z = fmaf(p, __half2float(g_Vh[((size_t)r * NN + n) * 128 + h * 32 + lane]), z);
        }
        float v = x[(size_t)n * 128 + h * 32 + lane] + z;
        t[h] = v;
        s1 += v;
        s2 = fmaf(v, v, s2);
    }
#pragma unroll
    for (int o = 16; o > 0; o >>= 1) {
        s1 += __shfl_xor_sync(0xffffffffu, s1, o);
        s2 += __shfl_xor_sync(0xffffffffu, s2, o);
    }
    float mu  = s1 * (1.0f / 128.0f);
    float var = s2 * (1.0f / 128.0f) - mu * mu;
    float rs  = rsqrtf(var + 1e-5f);
#pragma unroll
    for (int h = 0; h < 4; h++) {
        int c = h * 32 + lane;
        float hv = (t[h] - mu) * rs * g1[c] + be1[c];
        g_H  [(size_t)n * 128 + c] = hv;
        g_Hth[(size_t)n * 128 + c] = __float2half_rn(hv);
    }
}

// ---------------- launch ----------------
extern "C" void kernel_launch(void* const* d_in, const int* in_sizes, int n_in,
                              void* d_out, int out_size)
{
    const float* x   = (const float*)d_in[0];
    const int*   nbr = (const int*)  d_in[1];
    const float* wq  = (const float*)d_in[2];
    const float* wk  = (const float*)d_in[3];
    const float* wv  = (const float*)d_in[4];
    const float* W1  = (const float*)d_in[5];
    const float* b1  = (const float*)d_in[6];
    const float* W2  = (const float*)d_in[7];
    const float* b2  = (const float*)d_in[8];
    const float* g1  = (const float*)d_in[9];
    const float* be1 = (const float*)d_in[10];
    const float* g2  = (const float*)d_in[11];
    const float* be2 = (const float*)d_in[12];
    float* out = (float*)d_out;

    void *pXh, *pQh, *pH, *pHth, *pFh, *pWQ, *pW1, *pW2;
    cudaGetSymbolAddress(&pXh, g_Xh);
    cudaGetSymbolAddress(&pQh, g_Qh);
    cudaGetSymbolAddress(&pH,  g_H);
    cudaGetSymbolAddress(&pHth, g_Hth);
    cudaGetSymbolAddress(&pFh, g_Fh);
    cudaGetSymbolAddress(&pWQ, g_WQh);
    cudaGetSymbolAddress(&pW1, g_W1h);
    cudaGetSymbolAddress(&pW2, g_W2h);

    const size_t SMEM_AG = 32768 + (size_t)64 * 132 * sizeof(float);   // 66560
    const size_t SMEM_T2 = (size_t)128 * 132 * sizeof(float);          // 67584
    cudaFuncSetAttribute((const void*)agemm,
                         cudaFuncAttributeMaxDynamicSharedMemorySize, (int)SMEM_AG);
    cudaFuncSetAttribute((const void*)kv2,
                         cudaFuncAttributeMaxDynamicSharedMemorySize, (int)SMEM_AG);
    cudaFuncSetAttribute((const void*)tgemm2,
                         cudaFuncAttributeMaxDynamicSharedMemorySize, (int)SMEM_T2);

    const int GN = (NN + 127) / 128;   // 782

    conv_x_kernel<<<12500, 256>>>(x);
    trans_all<<<1216, 256>>>(wk, wv, wq, W1, W2);

    agemm<<<GN, 256, SMEM_AG>>>(
        (const __half*)pXh, (const __half*)pWQ, 1,
        (__half*)pQh, 128, 3, nullptr);

    kv2<<<dim3(GN, 1, 5), 256, SMEM_AG>>>(nbr);

    combine_ln1_kernel<<<NN / 8, 256>>>(x, g1, be1);

    agemm<<<GN, 256, SMEM_AG>>>(
        (const __half*)pHth, (const __half*)pW1, 4,
        (__half*)pFh, 512, 1, b1);

    tgemm2<<<GN, 256, SMEM_T2>>>(
        (const __half*)pFh, (const __half*)pW2,
        out, b2, (const float*)pH, g2, be2);
}

// round 14
// speedup vs baseline: 1.9401x; 1.2610x over previous
#include <cuda_runtime.h>
#include <cuda_fp16.h>
#include <cstdint>
#include <math.h>

#define NN 100000

// ---------------- scratch ----------------
__device__ __half g_Xh [(size_t)NN * 128];
__device__ __half g_Qh [(size_t)NN * 128];
__device__ __half g_Vh [(size_t)5 * NN * 128];
__device__ float  g_E  [(size_t)NN * 20];
__device__ float  g_H  [(size_t)NN * 128];
__device__ __half g_Hth[(size_t)NN * 128];
__device__ __half g_Fh [(size_t)NN * 512];
__device__ __half g_WQh [128 * 128];
__device__ __half g_WKVh[5 * 256 * 128];   // [r][c(K:0-127,V:128-255)][k]
__device__ __half g_W1h [512 * 128];
__device__ __half g_W2h [128 * 512];
__device__ float  g_denom[20];

__device__ __forceinline__ uint32_t smem_u32(const void* p) {
    uint32_t a;
    asm("{ .reg .u64 t; cvta.to.shared.u64 t, %1; cvt.u32.u64 %0, t; }" : "=r"(a) : "l"(p));
    return a;
}
__device__ __forceinline__ void cpa16(uint32_t dst, const void* src) {
    asm volatile("cp.async.ca.shared.global [%0], [%1], 16;" :: "r"(dst), "l"(src));
}

__global__ void conv_x_kernel(const float* __restrict__ x) {
    if (blockIdx.x == 0 && threadIdx.x < 20) g_denom[threadIdx.x] = 0.0f;
    size_t i = ((size_t)blockIdx.x * 256 + threadIdx.x) * 4;
    if (i >= (size_t)NN * 128) return;
    float4 v = *(const float4*)(x + i);
    *(__half2*)(g_Xh + i)     = __floats2half2_rn(v.x, v.y);
    *(__half2*)(g_Xh + i + 2) = __floats2half2_rn(v.z, v.w);
}

__global__ void trans_all(const float* __restrict__ wk, const float* __restrict__ wv,
                          const float* __restrict__ wq, const float* __restrict__ W1,
                          const float* __restrict__ W2) {
    int b = blockIdx.x;
    int tid = threadIdx.x;
    if (b < 640) {
        int z = b >> 7;
        int idx = (b & 127) * 256 + tid;
        int c = idx >> 7, k = idx & 127;
        float v;
        if (c < 128) {
            v = wk[(size_t)(c >> 5) * 20480 + (size_t)z * 4096 + k * 32 + (c & 31)];
        } else {
            int c2 = c - 128;
            v = wv[(size_t)(c2 >> 5) * 20480 + (size_t)z * 4096 + k * 32 + (c2 & 31)];
        }
        g_WKVh[(size_t)z * 32768 + idx] = __float2half_rn(v);
    } else {
        int b2 = b - 640;
        if (b2 < 64) {
            int idx = b2 * 256 + tid;
            int c = idx >> 7, k = idx & 127;
            g_WQh[idx] = __float2half_rn(wq[(size_t)(c >> 5) * 4096 + k * 32 + (c & 31)]);
        } else if (b2 < 320) {
            int idx = (b2 - 64) * 256 + tid;
            int c = idx >> 7, k = idx & 127;
            g_W1h[idx] = __float2half_rn(W1[(size_t)k * 512 + c]);
        } else {
            int idx = (b2 - 320) * 256 + tid;
            int c = idx >> 9, k = idx & 511;
            g_W2h[idx] = __float2half_rn(W2[(size_t)k * 128 + c]);
        }
    }
}

#define LDM_X4(r0,r1,r2,r3,addr) \
    asm volatile("ldmatrix.sync.aligned.m8n8.x4.shared.b16 {%0,%1,%2,%3}, [%4];" \
                 : "=r"(r0), "=r"(r1), "=r"(r2), "=r"(r3) : "r"(addr))
#define MMA_F16(dd,aa,bb) \
    asm volatile("mma.sync.aligned.m16n8k16.row.col.f32.f16.f16.f32 " \
                 "{%0,%1,%2,%3}, {%4,%5,%6,%7}, {%8,%9}, {%0,%1,%2,%3};" \
                 : "+f"((dd)[0]), "+f"((dd)[1]), "+f"((dd)[2]), "+f"((dd)[3]) \
                 : "r"((aa)[0]), "r"((aa)[1]), "r"((aa)[2]), "r"((aa)[3]), \
                   "r"((bb)[0]), "r"((bb)[1]))

__device__ __forceinline__ void chunk_mma(uint32_t abase, uint32_t bbase,
                                          int m0w, int n0w, int lane,
                                          float d[2][8][4]) {
    const int lrow = lane & 7;
    const int a_hi = (lane >> 3) >> 1, a_roff = ((lane >> 3) & 1) * 8;
    const int b_hi = (lane >> 3) & 1,  b_coff = (lane >> 4) * 8;
#pragma unroll
    for (int ks = 0; ks < 4; ++ks) {
        uint32_t a[2][4], b[8][2];
#pragma unroll
        for (int mf = 0; mf < 2; ++mf) {
            int r = m0w + mf * 16 + lrow + a_roff;
            uint32_t addr = abase + (uint32_t)r * 128u
                          + (uint32_t)(((2 * ks + a_hi) ^ lrow) << 4);
            LDM_X4(a[mf][0], a[mf][1], a[mf][2], a[mf][3], addr);
        }
#pragma unroll
        for (int pr = 0; pr < 4; ++pr) {
            int c = n0w + pr * 16 + lrow + b_coff;
            uint32_t addr = bbase + (uint32_t)c * 128u
                          + (uint32_t)(((2 * ks + b_hi) ^ (c & 7)) << 4);
            LDM_X4(b[2*pr][0], b[2*pr][1], b[2*pr+1][0], b[2*pr+1][1], addr);
        }
#pragma unroll
        for (int mf = 0; mf < 2; ++mf)
#pragma unroll
            for (int nf = 0; nf < 8; ++nf) MMA_F16(d[mf][nf], a[mf], b[nf]);
    }
}

#define ZERO_D(d) \
    { _Pragma("unroll") for (int i = 0; i < 2; i++) \
      _Pragma("unroll") for (int j = 0; j < 8; j++) \
      _Pragma("unroll") for (int q = 0; q < 4; q++) (d)[i][j][q] = 0.0f; }

// stage all accumulators as fp16 into sCh [128 rows][136 halfs (272B stride)]
// epi 1: bias+relu applied in register first
__device__ __forceinline__ void stage_h16(char* sCh, int m0w, int n0w, int lane,
                                          float d[2][8][4],
                                          int epi, const float* bias, int cg0) {
    const int g4 = lane >> 2, t4 = lane & 3;
#pragma unroll
    for (int mf = 0; mf < 2; ++mf)
#pragma unroll
        for (int nf = 0; nf < 8; ++nf) {
            int col = n0w + nf * 8 + t4 * 2;
            float b0 = 0.f, b1 = 0.f;
            if (epi == 1) { b0 = bias[cg0 + col]; b1 = bias[cg0 + col + 1]; }
#pragma unroll
            for (int rh = 0; rh < 2; ++rh) {
                int row = m0w + mf * 16 + g4 + rh * 8;
                float v0 = d[mf][nf][2*rh], v1 = d[mf][nf][2*rh+1];
                if (epi == 1) {
                    v0 = fmaxf(v0 + b0, 0.f);
                    v1 = fmaxf(v1 + b1, 0.f);
                }
                *(__half2*)(sCh + row * 272 + col * 2) = __floats2half2_rn(v0, v1);
            }
        }
}

// ---------------- agemm: A-resident GEMM (K=128), ny col-groups, overlapped --
__global__ __launch_bounds__(256, 2)
void agemm(const __half* __restrict__ A,
           const __half* __restrict__ BT,
           int ny,
           __half* __restrict__ Ch, int Cstride,
           int epi, const float* __restrict__ bias)
{
    extern __shared__ uint32_t sm[];
    char* smc = (char*)sm;
    const uint32_t sbase = smem_u32(smc);
    char* sCh = smc + 65536;                       // [128][272B]

    const int tid  = threadIdx.x;
    const int wid  = tid >> 5;
    const int lane = tid & 31;
    const int m0   = blockIdx.x * 128;
    const int m0w  = (wid >> 1) * 32;
    const int n0w  = (wid & 1) * 64;
    const int srow = tid >> 3, schk = tid & 7;

    // stage A resident (2 groups)
#pragma unroll
    for (int ch = 0; ch < 2; ++ch) {
#pragma unroll
        for (int p = 0; p < 4; ++p) {
            int row = srow + p * 32;
            int ar  = m0 + row; if (ar >= NN) ar = NN - 1;
            uint32_t off = (uint32_t)row * 128u + (uint32_t)((schk ^ (row & 7)) << 4);
            cpa16(sbase + ch * 16384u + off, A + (size_t)ar * 128 + ch * 64 + schk * 8);
        }
        asm volatile("cp.async.commit_group;" ::: "memory");
    }
    // stage B(0) (2 groups)
#pragma unroll
    for (int ch = 0; ch < 2; ++ch) {
#pragma unroll
        for (int p = 0; p < 4; ++p) {
            int row = srow + p * 32;
            uint32_t off = (uint32_t)row * 128u + (uint32_t)((schk ^ (row & 7)) << 4);
            cpa16(sbase + 32768u + ch * 16384u + off,
                  BT + (size_t)row * 128 + ch * 64 + schk * 8);
        }
        asm volatile("cp.async.commit_group;" ::: "memory");
    }

    for (int cy = 0; cy < ny; ++cy) {
        const int cg0 = cy * 128;
        float d[2][8][4];
        ZERO_D(d);
        asm volatile("cp.async.wait_group 1;" ::: "memory");
        __syncthreads();
        chunk_mma(sbase, sbase + 32768u, m0w, n0w, lane, d);
        asm volatile("cp.async.wait_group 0;" ::: "memory");
        __syncthreads();
        chunk_mma(sbase + 16384u, sbase + 49152u, m0w, n0w, lane, d);
        __syncthreads();   // B buffers free; prev store pass long done

        if (cy + 1 < ny) {
            const int cgn = (cy + 1) * 128;
#pragma unroll
            for (int ch = 0; ch < 2; ++ch) {
#pragma unroll
                for (int p = 0; p < 4; ++p) {
                    int row = srow + p * 32;
                    uint32_t off = (uint32_t)row * 128u + (uint32_t)((schk ^ (row & 7)) << 4);
                    cpa16(sbase + 32768u + ch * 16384u + off,
                          BT + (size_t)(cgn + row) * 128 + ch * 64 + schk * 8);
                }
                asm volatile("cp.async.commit_group;" ::: "memory");
            }
        }

        // fp16 staging (bias/relu in register), overlaps the B prefetch above
        stage_h16(sCh, m0w, n0w, lane, d, epi, bias, cg0);
        __syncthreads();

        // coalesced store: 8 x uint4 per thread
#pragma unroll
        for (int p = 0; p < 8; ++p) {
            int i   = tid + p * 256;
            int row = i >> 4;
            int u   = i & 15;
            int gr  = m0 + row;
            if (gr >= NN) continue;
            uint4 v = *(const uint4*)(sCh + row * 272 + u * 16);
            *(uint4*)(Ch + (size_t)gr * Cstride + cg0 + u * 8) = v;
        }
    }
}

// ---------------- kv2: fused K+V, register logits, fp16 V staging ------------
__global__ __launch_bounds__(256, 2)
void kv2(const int* __restrict__ nbr)
{
    extern __shared__ uint32_t sm[];
    char* smc = (char*)sm;
    const uint32_t sbase = smem_u32(smc);
    char* sCh = smc + 65536;                       // [128][272B]
    __shared__ int rowg[128];
    __shared__ float sden[20];

    const int tid  = threadIdx.x;
    const int wid  = tid >> 5;
    const int lane = tid & 31;
    const int g4   = lane >> 2, t4 = lane & 3;
    const int z    = blockIdx.z;
    const int m0   = blockIdx.x * 128;
    const int m0w  = (wid >> 1) * 32;
    const int n0w  = (wid & 1) * 64;
    const int srow = tid >> 3, schk = tid & 7;

    if (tid < 128) {
        int gr  = m0 + tid;
        int idx = (gr < NN) ? gr : (NN - 1);
        if (z > 0 && gr < NN) idx = nbr[gr * 4 + (z - 1)];
        rowg[tid] = idx;
    }
    if (tid < 20) sden[tid] = 0.0f;
    __syncthreads();

    const __half* Bz = g_WKVh + (size_t)z * 32768;

#pragma unroll
    for (int ch = 0; ch < 2; ++ch) {
#pragma unroll
        for (int p = 0; p < 4; ++p) {
            int row = srow + p * 32;
            uint32_t off = (uint32_t)row * 128u + (uint32_t)((schk ^ (row & 7)) << 4);
            cpa16(sbase + ch * 16384u + off,
                  g_Xh + (size_t)rowg[row] * 128 + ch * 64 + schk * 8);
        }
        asm volatile("cp.async.commit_group;" ::: "memory");
    }
#pragma unroll
    for (int ch = 0; ch < 2; ++ch) {
#pragma unroll
        for (int p = 0; p < 4; ++p) {
            int row = srow + p * 32;
            uint32_t off = (uint32_t)row * 128u + (uint32_t)((schk ^ (row & 7)) << 4);
            cpa16(sbase + 32768u + ch * 16384u + off,
                  Bz + (size_t)row * 128 + ch * 64 + schk * 8);
        }
        asm volatile("cp.async.commit_group;" ::: "memory");
    }

    float d[2][8][4];
    ZERO_D(d);
    asm volatile("cp.async.wait_group 1;" ::: "memory");
    __syncthreads();
    chunk_mma(sbase, sbase + 32768u, m0w, n0w, lane, d);
    asm volatile("cp.async.wait_group 0;" ::: "memory");
    __syncthreads();
    chunk_mma(sbase + 16384u, sbase + 49152u, m0w, n0w, lane, d);
    __syncthreads();   // all warps done reading B-K

    // prefetch B-V into freed B buffers (2 groups)
#pragma unroll
    for (int ch = 0; ch < 2; ++ch) {
#pragma unroll
        for (int p = 0; p < 4; ++p) {
            int row = srow + p * 32;
            uint32_t off = (uint32_t)row * 128u + (uint32_t)((schk ^ (row & 7)) << 4);
            cpa16(sbase + 32768u + ch * 16384u + off,
                  Bz + (size_t)(128 + row) * 128 + ch * 64 + schk * 8);
        }
        asm volatile("cp.async.commit_group;" ::: "memory");
    }

    // register-resident logits epilogue (overlaps B-V loads)
    {
        const float scale = 0.1767766952966369f;
        const int hbase = n0w >> 5;
        float esum0 = 0.f, esum1 = 0.f;
#pragma unroll
        for (int mf = 0; mf < 2; ++mf)
#pragma unroll
            for (int rh = 0; rh < 2; ++rh) {
                int gr = m0 + m0w + mf * 16 + g4 + rh * 8;
                bool valid = gr < NN;
                const __half2* qp = (const __half2*)(g_Qh + (size_t)(valid ? gr : 0) * 128);
#pragma unroll
                for (int hg = 0; hg < 2; ++hg) {
                    float s = 0.f;
#pragma unroll
                    for (int j = 0; j < 4; ++j) {
                        int nf = hg * 4 + j;
                        int col0 = n0w + nf * 8 + t4 * 2;
                        float2 qv = __half22float2(qp[col0 >> 1]);
                        s = fmaf(d[mf][nf][2*rh],     qv.x, s);
                        s = fmaf(d[mf][nf][2*rh + 1], qv.y, s);
                    }
                    s += __shfl_xor_sync(0xffffffffu, s, 1);
                    s += __shfl_xor_sync(0xffffffffu, s, 2);
                    if (t4 == 0 && valid) {
                        float e = expf(s * scale);
                        g_E[(size_t)gr * 20 + (hbase + hg) * 5 + z] = e;
                        if (hg == 0) esum0 += e; else esum1 += e;
                    }
                }
            }
        if (t4 == 0) {
            atomicAdd(&sden[(hbase + 0) * 5 + z], esum0);
            atomicAdd(&sden[(hbase + 1) * 5 + z], esum1);
        }
    }
    __syncthreads();
    if (tid < 20 && sden[tid] != 0.0f) atomicAdd(&g_denom[tid], sden[tid]);

    // V mainloop
    ZERO_D(d);
    asm volatile("cp.async.wait_group 1;" ::: "memory");
    __syncthreads();
    chunk_mma(sbase, sbase + 32768u, m0w, n0w, lane, d);
    asm volatile("cp.async.wait_group 0;" ::: "memory");
    __syncthreads();
    chunk_mma(sbase + 16384u, sbase + 49152u, m0w, n0w, lane, d);

    // V epilogue: single-pass fp16 staging + coalesced store
    stage_h16(sCh, m0w, n0w, lane, d, 3, nullptr, 0);
    __syncthreads();
#pragma unroll
    for (int p = 0; p < 8; ++p) {
        int i   = tid + p * 256;
        int row = i >> 4;
        int u   = i & 15;
        int gr  = m0 + row;
        if (gr >= NN) continue;
        uint4 v = *(const uint4*)(sCh + row * 272 + u * 16);
        *(uint4*)(g_Vh + ((size_t)z * NN + gr) * 128 + u * 8) = v;
    }
}

// ---------------- FFN2 GEMM (K=512) + resid + LN2 ----------------
__global__ __launch_bounds__(256, 2)
void tgemm2(const __half* __restrict__ A,
            const __half* __restrict__ BT,
            float* __restrict__ C,
            const float* __restrict__ bias,
            const float* __restrict__ resid,
            const float* __restrict__ gamma,
            const float* __restrict__ beta)
{
    extern __shared__ uint32_t sm[];
    char* smc = (char*)sm;
    const uint32_t sbase = smem_u32(smc);

    const int tid  = threadIdx.x;
    const int wid  = tid >> 5;
    const int lane = tid & 31;
    const int m0   = blockIdx.x * 128;
    const int m0w  = (wid >> 1) * 32;
    const int n0w  = (wid & 1) * 64;
    const int srow = tid >> 3, schk = tid & 7;

    float d[2][8][4];
    ZERO_D(d);

    auto stage = [&](int bsel, int kc) {
        const int kg0 = kc * 64;
        uint32_t abase = sbase + (uint32_t)bsel * 16384u;
        uint32_t bbase = sbase + 32768u + (uint32_t)bsel * 16384u;
#pragma unroll
        for (int p = 0; p < 4; ++p) {
            int row = srow + p * 32;
            int ar  = m0 + row; if (ar >= NN) ar = NN - 1;
            uint32_t off = (uint32_t)row * 128u + (uint32_t)((schk ^ (row & 7)) << 4);
            cpa16(abase + off, A + (size_t)ar * 512 + kg0 + schk * 8);
            cpa16(bbase + off, BT + (size_t)row * 512 + kg0 + schk * 8);
        }
        asm volatile("cp.async.commit_group;" ::: "memory");
    };

    stage(0, 0);
    for (int kc = 0; kc < 8; ++kc) {
        const int bsel = kc & 1;
        if (kc + 1 < 8) { stage(bsel ^ 1, kc + 1);
            asm volatile("cp.async.wait_group 1;" ::: "memory");
        } else { asm volatile("cp.async.wait_group 0;" ::: "memory"); }
        __syncthreads();
        chunk_mma(sbase + (uint32_t)bsel * 16384u,
                  sbase + 32768u + (uint32_t)bsel * 16384u, m0w, n0w, lane, d);
        __syncthreads();
    }

    float* sC = (float*)sm;
    const int g4 = lane >> 2, t4 = lane & 3;
#pragma unroll
    for (int mf = 0; mf < 2; ++mf)
#pragma unroll
        for (int nf = 0; nf < 8; ++nf) {
            int row = m0w + mf * 16 + g4;
            int col = n0w + nf * 8 + t4 * 2;
            *(float2*)(sC + row * 132 + col)       = make_float2(d[mf][nf][0], d[mf][nf][1]);
            *(float2*)(sC + (row + 8) * 132 + col) = make_float2(d[mf][nf][2], d[mf][nf][3]);
        }
    __syncthreads();

    for (int rr = wid; rr < 128; rr += 8) {
        int gr = m0 + rr;
        if (gr >= NN) continue;
        const float* rp = resid + (size_t)gr * 128;
        float v0 = sC[rr * 132 + lane]      + bias[lane]      + rp[lane];
        float v1 = sC[rr * 132 + 32 + lane] + bias[32 + lane] + rp[32 + lane];
        float v2 = sC[rr * 132 + 64 + lane] + bias[64 + lane] + rp[64 + lane];
        float v3 = sC[rr * 132 + 96 + lane] + bias[96 + lane] + rp[96 + lane];
        float s1 = v0 + v1 + v2 + v3;
        float s2 = v0 * v0 + v1 * v1 + v2 * v2 + v3 * v3;
#pragma unroll
        for (int o = 16; o > 0; o >>= 1) {
            s1 += __shfl_xor_sync(0xffffffffu, s1, o);
            s2 += __shfl_xor_sync(0xffffffffu, s2, o);
        }
        float mu  = s1 * (1.0f / 128.0f);
        float var = s2 * (1.0f / 128.0f) - mu * mu;
        float rs  = rsqrtf(var + 1e-5f);
        float* dst = C + (size_t)gr * 128;
        dst[lane]      = (v0 - mu) * rs * gamma[lane]      + beta[lane];
        dst[lane + 32] = (v1 - mu) * rs * gamma[lane + 32] + beta[lane + 32];
        dst[lane + 64] = (v2 - mu) * rs * gamma[lane + 64] + beta[lane + 64];
        dst[lane + 96] = (v3 - mu) * rs * gamma[lane + 96] + beta[lane + 96];
    }
}

// ---------------- combine + residual + LN1 (vectorized) ----------------
__global__ void combine_ln1_kernel(const float* __restrict__ x,
                                   const float* __restrict__ g1,
                                   const float* __restrict__ be1) {
    __shared__ float sinv[20];
    const int tid = threadIdx.x;
    if (tid < 20) sinv[tid] = 1.0f / g_denom[tid];
    __syncthreads();
    const int n    = blockIdx.x * 8 + (tid >> 5);
    const int lane = tid & 31;
    if (n >= NN) return;

    float pv = 0.0f;
    if (lane < 20) pv = g_E[(size_t)n * 20 + lane] * sinv[lane];

    float2 t[2];
    float s1 = 0.0f, s2 = 0.0f;
#pragma unroll
    for (int g = 0; g < 2; ++g) {
        int c = g * 64 + 2 * lane;
        int h = c >> 5;
        float2 zz = make_float2(0.f, 0.f);
#pragma unroll
        for (int r = 0; r < 5; ++r) {
            float p = __shfl_sync(0xffffffffu, pv, h * 5 + r);
            __half2 vh = *(const __half2*)(g_Vh + ((size_t)r * NN + n) * 128 + c);
            float2 vf = __half22float2(vh);
            zz.x = fmaf(p, vf.x, zz.x);
            zz.y = fmaf(p, vf.y, zz.y);
        }
        float2 xv = *(const float2*)(x + (size_t)n * 128 + c);
        float2 v = make_float2(xv.x + zz.x, xv.y + zz.y);
        t[g] = v;
        s1 += v.x + v.y;
        s2 = fmaf(v.x, v.x, fmaf(v.y, v.y, s2));
    }
#pragma unroll
    for (int o = 16; o > 0; o >>= 1) {
        s1 += __shfl_xor_sync(0xffffffffu, s1, o);
        s2 += __shfl_xor_sync(0xffffffffu, s2, o);
    }
    float mu  = s1 * (1.0f / 128.0f);
    float var = s2 * (1.0f / 128.0f) - mu * mu;
    float rs  = rsqrtf(var + 1e-5f);
#pragma unroll
    for (int g = 0; g < 2; ++g) {
        int c = g * 64 + 2 * lane;
        float o0 = (t[g].x - mu) * rs * g1[c]     + be1[c];
        float o1 = (t[g].y - mu) * rs * g1[c + 1] + be1[c + 1];
        *(float2*)(g_H + (size_t)n * 128 + c) = make_float2(o0, o1);
        *(__half2*)(g_Hth + (size_t)n * 128 + c) = __floats2half2_rn(o0, o1);
    }
}

// ---------------- launch ----------------
extern "C" void kernel_launch(void* const* d_in, const int* in_sizes, int n_in,
                              void* d_out, int out_size)
{
    const float* x   = (const float*)d_in[0];
    const int*   nbr = (const int*)  d_in[1];
    const float* wq  = (const float*)d_in[2];
    const float* wk  = (const float*)d_in[3];
    const float* wv  = (const float*)d_in[4];
    const float* W1  = (const float*)d_in[5];
    const float* b1  = (const float*)d_in[6];
    const float* W2  = (const float*)d_in[7];
    const float* b2  = (const float*)d_in[8];
    const float* g1  = (const float*)d_in[9];
    const float* be1 = (const float*)d_in[10];
    const float* g2  = (const float*)d_in[11];
    const float* be2 = (const float*)d_in[12];
    float* out = (float*)d_out;

    void *pXh, *pQh, *pH, *pHth, *pFh, *pWQ, *pW1, *pW2;
    cudaGetSymbolAddress(&pXh, g_Xh);
    cudaGetSymbolAddress(&pQh, g_Qh);
    cudaGetSymbolAddress(&pH,  g_H);
    cudaGetSymbolAddress(&pHth, g_Hth);
    cudaGetSymbolAddress(&pFh, g_Fh);
    cudaGetSymbolAddress(&pWQ, g_WQh);
    cudaGetSymbolAddress(&pW1, g_W1h);
    cudaGetSymbolAddress(&pW2, g_W2h);

    const size_t SMEM_AG = 65536 + 128 * 272;        // 100352
    const size_t SMEM_T2 = (size_t)128 * 132 * sizeof(float);   // 67584
    cudaFuncSetAttribute((const void*)agemm,
                         cudaFuncAttributeMaxDynamicSharedMemorySize, (int)SMEM_AG);
    cudaFuncSetAttribute((const void*)kv2,
                         cudaFuncAttributeMaxDynamicSharedMemorySize, (int)SMEM_AG);
    cudaFuncSetAttribute((const void*)tgemm2,
                         cudaFuncAttributeMaxDynamicSharedMemorySize, (int)SMEM_T2);

    const int GN = (NN + 127) / 128;   // 782

    conv_x_kernel<<<12500, 256>>>(x);
    trans_all<<<1216, 256>>>(wk, wv, wq, W1, W2);

    agemm<<<GN, 256, SMEM_AG>>>(
        (const __half*)pXh, (const __half*)pWQ, 1,
        (__half*)pQh, 128, 3, nullptr);

    kv2<<<dim3(GN, 1, 5), 256, SMEM_AG>>>(nbr);

    combine_ln1_kernel<<<NN / 8, 256>>>(x, g1, be1);

    agemm<<<GN, 256, SMEM_AG>>>(
        (const __half*)pHth, (const __half*)pW1, 4,
        (__half*)pFh, 512, 1, b1);

    tgemm2<<<GN, 256, SMEM_T2>>>(
        (const __half*)pFh, (const __half*)pW2,
        out, b2, (const float*)pH, g2, be2);
}

// round 15
// speedup vs baseline: 2.0397x; 1.0513x over previous
#include <cuda_runtime.h>
#include <cuda_fp16.h>
#include <cstdint>
#include <math.h>

#define NN 100000

// ---------------- scratch ----------------
__device__ __half g_Xh [(size_t)NN * 128];
__device__ __half g_Qh [(size_t)NN * 128];
__device__ __half g_Vh [(size_t)5 * NN * 128];
__device__ float  g_E  [(size_t)NN * 20];
__device__ __half g_Hth[(size_t)NN * 128];     // fp16 H (GEMM input AND residual)
__device__ __half g_Fh [(size_t)NN * 512];
__device__ __half g_WQh [128 * 128];
__device__ __half g_WKVh[5 * 256 * 128];   // [r][c(K:0-127,V:128-255)][k]
__device__ __half g_W1h [512 * 128];
__device__ __half g_W2h [128 * 512];
__device__ float  g_denom[20];

__device__ __forceinline__ uint32_t smem_u32(const void* p) {
    uint32_t a;
    asm("{ .reg .u64 t; cvta.to.shared.u64 t, %1; cvt.u32.u64 %0, t; }" : "=r"(a) : "l"(p));
    return a;
}
__device__ __forceinline__ void cpa16(uint32_t dst, const void* src) {
    asm volatile("cp.async.ca.shared.global [%0], [%1], 16;" :: "r"(dst), "l"(src));
}

__global__ void conv_x_kernel(const float* __restrict__ x) {
    if (blockIdx.x == 0 && threadIdx.x < 20) g_denom[threadIdx.x] = 0.0f;
    size_t i = ((size_t)blockIdx.x * 256 + threadIdx.x) * 4;
    if (i >= (size_t)NN * 128) return;
    float4 v = *(const float4*)(x + i);
    *(__half2*)(g_Xh + i)     = __floats2half2_rn(v.x, v.y);
    *(__half2*)(g_Xh + i + 2) = __floats2half2_rn(v.z, v.w);
}

__global__ void trans_all(const float* __restrict__ wk, const float* __restrict__ wv,
                          const float* __restrict__ wq, const float* __restrict__ W1,
                          const float* __restrict__ W2) {
    int b = blockIdx.x;
    int tid = threadIdx.x;
    if (b < 640) {
        int z = b >> 7;
        int idx = (b & 127) * 256 + tid;
        int c = idx >> 7, k = idx & 127;
        float v;
        if (c < 128) {
            v = wk[(size_t)(c >> 5) * 20480 + (size_t)z * 4096 + k * 32 + (c & 31)];
        } else {
            int c2 = c - 128;
            v = wv[(size_t)(c2 >> 5) * 20480 + (size_t)z * 4096 + k * 32 + (c2 & 31)];
        }
        g_WKVh[(size_t)z * 32768 + idx] = __float2half_rn(v);
    } else {
        int b2 = b - 640;
        if (b2 < 64) {
            int idx = b2 * 256 + tid;
            int c = idx >> 7, k = idx & 127;
            g_WQh[idx] = __float2half_rn(wq[(size_t)(c >> 5) * 4096 + k * 32 + (c & 31)]);
        } else if (b2 < 320) {
            int idx = (b2 - 64) * 256 + tid;
            int c = idx >> 7, k = idx & 127;
            g_W1h[idx] = __float2half_rn(W1[(size_t)k * 512 + c]);
        } else {
            int idx = (b2 - 320) * 256 + tid;
            int c = idx >> 9, k = idx & 511;
            g_W2h[idx] = __float2half_rn(W2[(size_t)k * 128 + c]);
        }
    }
}

#define LDM_X4(r0,r1,r2,r3,addr) \
    asm volatile("ldmatrix.sync.aligned.m8n8.x4.shared.b16 {%0,%1,%2,%3}, [%4];" \
                 : "=r"(r0), "=r"(r1), "=r"(r2), "=r"(r3) : "r"(addr))
#define MMA_F16(dd,aa,bb) \
    asm volatile("mma.sync.aligned.m16n8k16.row.col.f32.f16.f16.f32 " \
                 "{%0,%1,%2,%3}, {%4,%5,%6,%7}, {%8,%9}, {%0,%1,%2,%3};" \
                 : "+f"((dd)[0]), "+f"((dd)[1]), "+f"((dd)[2]), "+f"((dd)[3]) \
                 : "r"((aa)[0]), "r"((aa)[1]), "r"((aa)[2]), "r"((aa)[3]), \
                   "r"((bb)[0]), "r"((bb)[1]))

__device__ __forceinline__ void chunk_mma(uint32_t abase, uint32_t bbase,
                                          int m0w, int n0w, int lane,
                                          float d[2][8][4]) {
    const int lrow = lane & 7;
    const int a_hi = (lane >> 3) >> 1, a_roff = ((lane >> 3) & 1) * 8;
    const int b_hi = (lane >> 3) & 1,  b_coff = (lane >> 4) * 8;
#pragma unroll
    for (int ks = 0; ks < 4; ++ks) {
        uint32_t a[2][4], b[8][2];
#pragma unroll
        for (int mf = 0; mf < 2; ++mf) {
            int r = m0w + mf * 16 + lrow + a_roff;
            uint32_t addr = abase + (uint32_t)r * 128u
                          + (uint32_t)(((2 * ks + a_hi) ^ lrow) << 4);
            LDM_X4(a[mf][0], a[mf][1], a[mf][2], a[mf][3], addr);
        }
#pragma unroll
        for (int pr = 0; pr < 4; ++pr) {
            int c = n0w + pr * 16 + lrow + b_coff;
            uint32_t addr = bbase + (uint32_t)c * 128u
                          + (uint32_t)(((2 * ks + b_hi) ^ (c & 7)) << 4);
            LDM_X4(b[2*pr][0], b[2*pr][1], b[2*pr+1][0], b[2*pr+1][1], addr);
        }
#pragma unroll
        for (int mf = 0; mf < 2; ++mf)
#pragma unroll
            for (int nf = 0; nf < 8; ++nf) MMA_F16(d[mf][nf], a[mf], b[nf]);
    }
}

#define ZERO_D(d) \
    { _Pragma("unroll") for (int i = 0; i < 2; i++) \
      _Pragma("unroll") for (int j = 0; j < 8; j++) \
      _Pragma("unroll") for (int q = 0; q < 4; q++) (d)[i][j][q] = 0.0f; }

// stage accumulators as fp16 into sCh [128 rows][272B stride]
__device__ __forceinline__ void stage_h16(char* sCh, int m0w, int n0w, int lane,
                                          float d[2][8][4],
                                          int epi, const float* bias, int cg0) {
    const int g4 = lane >> 2, t4 = lane & 3;
#pragma unroll
    for (int mf = 0; mf < 2; ++mf)
#pragma unroll
        for (int nf = 0; nf < 8; ++nf) {
            int col = n0w + nf * 8 + t4 * 2;
            float b0 = 0.f, b1 = 0.f;
            if (epi == 1) { b0 = bias[cg0 + col]; b1 = bias[cg0 + col + 1]; }
#pragma unroll
            for (int rh = 0; rh < 2; ++rh) {
                int row = m0w + mf * 16 + g4 + rh * 8;
                float v0 = d[mf][nf][2*rh], v1 = d[mf][nf][2*rh+1];
                if (epi == 1) {
                    v0 = fmaxf(v0 + b0, 0.f);
                    v1 = fmaxf(v1 + b1, 0.f);
                }
                *(__half2*)(sCh + row * 272 + col * 2) = __floats2half2_rn(v0, v1);
            }
        }
}

// ---------------- agemm: A-resident GEMM (K=128), ny col-groups --------------
__global__ __launch_bounds__(256, 2)
void agemm(const __half* __restrict__ A,
           const __half* __restrict__ BT,
           int ny,
           __half* __restrict__ Ch, int Cstride,
           int epi, const float* __restrict__ bias)
{
    extern __shared__ uint32_t sm[];
    char* smc = (char*)sm;
    const uint32_t sbase = smem_u32(smc);
    char* sCh = smc + 65536;

    const int tid  = threadIdx.x;
    const int wid  = tid >> 5;
    const int lane = tid & 31;
    const int m0   = blockIdx.x * 128;
    const int m0w  = (wid >> 1) * 32;
    const int n0w  = (wid & 1) * 64;
    const int srow = tid >> 3, schk = tid & 7;

#pragma unroll
    for (int ch = 0; ch < 2; ++ch) {
#pragma unroll
        for (int p = 0; p < 4; ++p) {
            int row = srow + p * 32;
            int ar  = m0 + row; if (ar >= NN) ar = NN - 1;
            uint32_t off = (uint32_t)row * 128u + (uint32_t)((schk ^ (row & 7)) << 4);
            cpa16(sbase + ch * 16384u + off, A + (size_t)ar * 128 + ch * 64 + schk * 8);
        }
        asm volatile("cp.async.commit_group;" ::: "memory");
    }
#pragma unroll
    for (int ch = 0; ch < 2; ++ch) {
#pragma unroll
        for (int p = 0; p < 4; ++p) {
            int row = srow + p * 32;
            uint32_t off = (uint32_t)row * 128u + (uint32_t)((schk ^ (row & 7)) << 4);
            cpa16(sbase + 32768u + ch * 16384u + off,
                  BT + (size_t)row * 128 + ch * 64 + schk * 8);
        }
        asm volatile("cp.async.commit_group;" ::: "memory");
    }

    for (int cy = 0; cy < ny; ++cy) {
        const int cg0 = cy * 128;
        float d[2][8][4];
        ZERO_D(d);
        asm volatile("cp.async.wait_group 1;" ::: "memory");
        __syncthreads();
        chunk_mma(sbase, sbase + 32768u, m0w, n0w, lane, d);
        asm volatile("cp.async.wait_group 0;" ::: "memory");
        __syncthreads();
        chunk_mma(sbase + 16384u, sbase + 49152u, m0w, n0w, lane, d);
        __syncthreads();

        if (cy + 1 < ny) {
            const int cgn = (cy + 1) * 128;
#pragma unroll
            for (int ch = 0; ch < 2; ++ch) {
#pragma unroll
                for (int p = 0; p < 4; ++p) {
                    int row = srow + p * 32;
                    uint32_t off = (uint32_t)row * 128u + (uint32_t)((schk ^ (row & 7)) << 4);
                    cpa16(sbase + 32768u + ch * 16384u + off,
                          BT + (size_t)(cgn + row) * 128 + ch * 64 + schk * 8);
                }
                asm volatile("cp.async.commit_group;" ::: "memory");
            }
        }

        stage_h16(sCh, m0w, n0w, lane, d, epi, bias, cg0);
        __syncthreads();

#pragma unroll
        for (int p = 0; p < 8; ++p) {
            int i   = tid + p * 256;
            int row = i >> 4;
            int u   = i & 15;
            int gr  = m0 + row;
            if (gr >= NN) continue;
            uint4 v = *(const uint4*)(sCh + row * 272 + u * 16);
            *(uint4*)(Ch + (size_t)gr * Cstride + cg0 + u * 8) = v;
        }
    }
}

// ---------------- kv2: fused K+V, smem Q logits, fp16 V staging --------------
__global__ __launch_bounds__(256, 2)
void kv2(const int* __restrict__ nbr)
{
    extern __shared__ uint32_t sm[];
    char* smc = (char*)sm;
    const uint32_t sbase = smem_u32(smc);
    char* sCh = smc + 65536;                 // Q tile during K phase; V staging later
    const uint32_t qbase = sbase + 65536u;
    __shared__ int rowg[128];
    __shared__ float sden[20];

    const int tid  = threadIdx.x;
    const int wid  = tid >> 5;
    const int lane = tid & 31;
    const int g4   = lane >> 2, t4 = lane & 3;
    const int z    = blockIdx.z;
    const int m0   = blockIdx.x * 128;
    const int m0w  = (wid >> 1) * 32;
    const int n0w  = (wid & 1) * 64;
    const int srow = tid >> 3, schk = tid & 7;

    if (tid < 128) {
        int gr  = m0 + tid;
        int idx = (gr < NN) ? gr : (NN - 1);
        if (z > 0 && gr < NN) idx = nbr[gr * 4 + (z - 1)];
        rowg[tid] = idx;
    }
    if (tid < 20) sden[tid] = 0.0f;
    __syncthreads();

    const __half* Bz = g_WKVh + (size_t)z * 32768;

    // groups 1,2: A ; 3,4: B-K ; 5: Q tile (128 rows x 256B, 272B stride)
#pragma unroll
    for (int ch = 0; ch < 2; ++ch) {
#pragma unroll
        for (int p = 0; p < 4; ++p) {
            int row = srow + p * 32;
            uint32_t off = (uint32_t)row * 128u + (uint32_t)((schk ^ (row & 7)) << 4);
            cpa16(sbase + ch * 16384u + off,
                  g_Xh + (size_t)rowg[row] * 128 + ch * 64 + schk * 8);
        }
        asm volatile("cp.async.commit_group;" ::: "memory");
    }
#pragma unroll
    for (int ch = 0; ch < 2; ++ch) {
#pragma unroll
        for (int p = 0; p < 4; ++p) {
            int row = srow + p * 32;
            uint32_t off = (uint32_t)row * 128u + (uint32_t)((schk ^ (row & 7)) << 4);
            cpa16(sbase + 32768u + ch * 16384u + off,
                  Bz + (size_t)row * 128 + ch * 64 + schk * 8);
        }
        asm volatile("cp.async.commit_group;" ::: "memory");
    }
    {
        // Q: 2048 16B chunks; thread covers 8
#pragma unroll
        for (int p = 0; p < 8; ++p) {
            int i   = tid + p * 256;
            int row = i >> 4;
            int u   = i & 15;
            int gr  = m0 + row; if (gr >= NN) gr = NN - 1;
            cpa16(qbase + (uint32_t)row * 272u + (uint32_t)u * 16u,
                  g_Qh + (size_t)gr * 128 + u * 8);
        }
        asm volatile("cp.async.commit_group;" ::: "memory");
    }

    float d[2][8][4];
    ZERO_D(d);
    asm volatile("cp.async.wait_group 2;" ::: "memory");   // A0,A1,BK0 done
    __syncthreads();
    chunk_mma(sbase, sbase + 32768u, m0w, n0w, lane, d);
    asm volatile("cp.async.wait_group 1;" ::: "memory");   // BK1 done (Q may lag)
    __syncthreads();
    chunk_mma(sbase + 16384u, sbase + 49152u, m0w, n0w, lane, d);
    __syncthreads();   // all warps done reading B-K

    // groups 6,7: prefetch B-V into freed B buffers
#pragma unroll
    for (int ch = 0; ch < 2; ++ch) {
#pragma unroll
        for (int p = 0; p < 4; ++p) {
            int row = srow + p * 32;
            uint32_t off = (uint32_t)row * 128u + (uint32_t)((schk ^ (row & 7)) << 4);
            cpa16(sbase + 32768u + ch * 16384u + off,
                  Bz + (size_t)(128 + row) * 128 + ch * 64 + schk * 8);
        }
        asm volatile("cp.async.commit_group;" ::: "memory");
    }

    // Q must be visible to all threads before smem logits
    asm volatile("cp.async.wait_group 2;" ::: "memory");   // Q done; BV0,BV1 may lag
    __syncthreads();

    // register-resident logits epilogue, Q read from smem
    {
        const float scale = 0.1767766952966369f;
        const int hbase = n0w >> 5;
        float esum0 = 0.f, esum1 = 0.f;
#pragma unroll
        for (int mf = 0; mf < 2; ++mf)
#pragma unroll
            for (int rh = 0; rh < 2; ++rh) {
                int lrowq = m0w + mf * 16 + g4 + rh * 8;
                int gr = m0 + lrowq;
                bool valid = gr < NN;
#pragma unroll
                for (int hg = 0; hg < 2; ++hg) {
                    float s = 0.f;
#pragma unroll
                    for (int j = 0; j < 4; ++j) {
                        int nf = hg * 4 + j;
                        int col0 = n0w + nf * 8 + t4 * 2;
                        float2 qv = __half22float2(
                            *(const __half2*)(sCh + lrowq * 272 + col0 * 2));
                        s = fmaf(d[mf][nf][2*rh],     qv.x, s);
                        s = fmaf(d[mf][nf][2*rh + 1], qv.y, s);
                    }
                    s += __shfl_xor_sync(0xffffffffu, s, 1);
                    s += __shfl_xor_sync(0xffffffffu, s, 2);
                    if (t4 == 0 && valid) {
                        float e = expf(s * scale);
                        g_E[(size_t)gr * 20 + (hbase + hg) * 5 + z] = e;
                        if (hg == 0) esum0 += e; else esum1 += e;
                    }
                }
            }
        if (t4 == 0) {
            atomicAdd(&sden[(hbase + 0) * 5 + z], esum0);
            atomicAdd(&sden[(hbase + 1) * 5 + z], esum1);
        }
    }
    __syncthreads();
    if (tid < 20 && sden[tid] != 0.0f) atomicAdd(&g_denom[tid], sden[tid]);

    // V mainloop
    ZERO_D(d);
    asm volatile("cp.async.wait_group 1;" ::: "memory");
    __syncthreads();
    chunk_mma(sbase, sbase + 32768u, m0w, n0w, lane, d);
    asm volatile("cp.async.wait_group 0;" ::: "memory");
    __syncthreads();
    chunk_mma(sbase + 16384u, sbase + 49152u, m0w, n0w, lane, d);
    __syncthreads();   // Q smem reads done before sCh overwrite (also above)

    // V epilogue: fp16 staging + coalesced store
    stage_h16(sCh, m0w, n0w, lane, d, 3, nullptr, 0);
    __syncthreads();
#pragma unroll
    for (int p = 0; p < 8; ++p) {
        int i   = tid + p * 256;
        int row = i >> 4;
        int u   = i & 15;
        int gr  = m0 + row;
        if (gr >= NN) continue;
        uint4 v = *(const uint4*)(sCh + row * 272 + u * 16);
        *(uint4*)(g_Vh + ((size_t)z * NN + gr) * 128 + u * 8) = v;
    }
}

// ---------------- FFN2 GEMM (K=512) + fp16 resid + LN2 ----------------
__global__ __launch_bounds__(256, 2)
void tgemm2(const __half* __restrict__ A,
            const __half* __restrict__ BT,
            float* __restrict__ C,
            const float* __restrict__ bias,
            const __half* __restrict__ resid,
            const float* __restrict__ gamma,
            const float* __restrict__ beta)
{
    extern __shared__ uint32_t sm[];
    char* smc = (char*)sm;
    const uint32_t sbase = smem_u32(smc);

    const int tid  = threadIdx.x;
    const int wid  = tid >> 5;
    const int lane = tid & 31;
    const int m0   = blockIdx.x * 128;
    const int m0w  = (wid >> 1) * 32;
    const int n0w  = (wid & 1) * 64;
    const int srow = tid >> 3, schk = tid & 7;

    float d[2][8][4];
    ZERO_D(d);

    auto stage = [&](int bsel, int kc) {
        const int kg0 = kc * 64;
        uint32_t abase = sbase + (uint32_t)bsel * 16384u;
        uint32_t bbase = sbase + 32768u + (uint32_t)bsel * 16384u;
#pragma unroll
        for (int p = 0; p < 4; ++p) {
            int row = srow + p * 32;
            int ar  = m0 + row; if (ar >= NN) ar = NN - 1;
            uint32_t off = (uint32_t)row * 128u + (uint32_t)((schk ^ (row & 7)) << 4);
            cpa16(abase + off, A + (size_t)ar * 512 + kg0 + schk * 8);
            cpa16(bbase + off, BT + (size_t)row * 512 + kg0 + schk * 8);
        }
        asm volatile("cp.async.commit_group;" ::: "memory");
    };

    stage(0, 0);
    for (int kc = 0; kc < 8; ++kc) {
        const int bsel = kc & 1;
        if (kc + 1 < 8) { stage(bsel ^ 1, kc + 1);
            asm volatile("cp.async.wait_group 1;" ::: "memory");
        } else { asm volatile("cp.async.wait_group 0;" ::: "memory"); }
        __syncthreads();
        chunk_mma(sbase + (uint32_t)bsel * 16384u,
                  sbase + 32768u + (uint32_t)bsel * 16384u, m0w, n0w, lane, d);
        __syncthreads();
    }

    float* sC = (float*)sm;
    const int g4 = lane >> 2, t4 = lane & 3;
#pragma unroll
    for (int mf = 0; mf < 2; ++mf)
#pragma unroll
        for (int nf = 0; nf < 8; ++nf) {
            int row = m0w + mf * 16 + g4;
            int col = n0w + nf * 8 + t4 * 2;
            *(float2*)(sC + row * 132 + col)       = make_float2(d[mf][nf][0], d[mf][nf][1]);
            *(float2*)(sC + (row + 8) * 132 + col) = make_float2(d[mf][nf][2], d[mf][nf][3]);
        }
    __syncthreads();

    for (int rr = wid; rr < 128; rr += 8) {
        int gr = m0 + rr;
        if (gr >= NN) continue;
        const __half* rp = resid + (size_t)gr * 128;
        float v0 = sC[rr * 132 + lane]      + bias[lane]      + __half2float(rp[lane]);
        float v1 = sC[rr * 132 + 32 + lane] + bias[32 + lane] + __half2float(rp[32 + lane]);
        float v2 = sC[rr * 132 + 64 + lane] + bias[64 + lane] + __half2float(rp[64 + lane]);
        float v3 = sC[rr * 132 + 96 + lane] + bias[96 + lane] + __half2float(rp[96 + lane]);
        float s1 = v0 + v1 + v2 + v3;
        float s2 = v0 * v0 + v1 * v1 + v2 * v2 + v3 * v3;
#pragma unroll
        for (int o = 16; o > 0; o >>= 1) {
            s1 += __shfl_xor_sync(0xffffffffu, s1, o);
            s2 += __shfl_xor_sync(0xffffffffu, s2, o);
        }
        float mu  = s1 * (1.0f / 128.0f);
        float var = s2 * (1.0f / 128.0f) - mu * mu;
        float rs  = rsqrtf(var + 1e-5f);
        float* dst = C + (size_t)gr * 128;
        dst[lane]      = (v0 - mu) * rs * gamma[lane]      + beta[lane];
        dst[lane + 32] = (v1 - mu) * rs * gamma[lane + 32] + beta[lane + 32];
        dst[lane + 64] = (v2 - mu) * rs * gamma[lane + 64] + beta[lane + 64];
        dst[lane + 96] = (v3 - mu) * rs * gamma[lane + 96] + beta[lane + 96];
    }
}

// ---------------- combine + residual + LN1 (fp16 H only) ----------------
__global__ void combine_ln1_kernel(const float* __restrict__ x,
                                   const float* __restrict__ g1,
                                   const float* __restrict__ be1) {
    __shared__ float sinv[20];
    const int tid = threadIdx.x;
    if (tid < 20) sinv[tid] = 1.0f / g_denom[tid];
    __syncthreads();
    const int n    = blockIdx.x * 8 + (tid >> 5);
    const int lane = tid & 31;
    if (n >= NN) return;

    float pv = 0.0f;
    if (lane < 20) pv = g_E[(size_t)n * 20 + lane] * sinv[lane];

    float2 t[2];
    float s1 = 0.0f, s2 = 0.0f;
#pragma unroll
    for (int g = 0; g < 2; ++g) {
        int c = g * 64 + 2 * lane;
        int h = c >> 5;
        float2 zz = make_float2(0.f, 0.f);
#pragma unroll
        for (int r = 0; r < 5; ++r) {
            float p = __shfl_sync(0xffffffffu, pv, h * 5 + r);
            __half2 vh = *(const __half2*)(g_Vh + ((size_t)r * NN + n) * 128 + c);
            float2 vf = __half22float2(vh);
            zz.x = fmaf(p, vf.x, zz.x);
            zz.y = fmaf(p, vf.y, zz.y);
        }
        float2 xv = *(const float2*)(x + (size_t)n * 128 + c);
        float2 v = make_float2(xv.x + zz.x, xv.y + zz.y);
        t[g] = v;
        s1 += v.x + v.y;
        s2 = fmaf(v.x, v.x, fmaf(v.y, v.y, s2));
    }
#pragma unroll
    for (int o = 16; o > 0; o >>= 1) {
        s1 += __shfl_xor_sync(0xffffffffu, s1, o);
        s2 += __shfl_xor_sync(0xffffffffu, s2, o);
    }
    float mu  = s1 * (1.0f / 128.0f);
    float var = s2 * (1.0f / 128.0f) - mu * mu;
    float rs  = rsqrtf(var + 1e-5f);
#pragma unroll
    for (int g = 0; g < 2; ++g) {
        int c = g * 64 + 2 * lane;
        float o0 = (t[g].x - mu) * rs * g1[c]     + be1[c];
        float o1 = (t[g].y - mu) * rs * g1[c + 1] + be1[c + 1];
        *(__half2*)(g_Hth + (size_t)n * 128 + c) = __floats2half2_rn(o0, o1);
    }
}

// ---------------- launch ----------------
extern "C" void kernel_launch(void* const* d_in, const int* in_sizes, int n_in,
                              void* d_out, int out_size)
{
    const float* x   = (const float*)d_in[0];
    const int*   nbr = (const int*)  d_in[1];
    const float* wq  = (const float*)d_in[2];
    const float* wk  = (const float*)d_in[3];
    const float* wv  = (const float*)d_in[4];
    const float* W1  = (const float*)d_in[5];
    const float* b1  = (const float*)d_in[6];
    const float* W2  = (const float*)d_in[7];
    const float* b2  = (const float*)d_in[8];
    const float* g1  = (const float*)d_in[9];
    const float* be1 = (const float*)d_in[10];
    const float* g2  = (const float*)d_in[11];
    const float* be2 = (const float*)d_in[12];
    float* out = (float*)d_out;

    void *pXh, *pQh, *pHth, *pFh, *pWQ, *pW1, *pW2;
    cudaGetSymbolAddress(&pXh, g_Xh);
    cudaGetSymbolAddress(&pQh, g_Qh);
    cudaGetSymbolAddress(&pHth, g_Hth);
    cudaGetSymbolAddress(&pFh, g_Fh);
    cudaGetSymbolAddress(&pWQ, g_WQh);
    cudaGetSymbolAddress(&pW1, g_W1h);
    cudaGetSymbolAddress(&pW2, g_W2h);

    const size_t SMEM_AG = 65536 + 128 * 272;                   // 100352
    const size_t SMEM_T2 = (size_t)128 * 132 * sizeof(float);   // 67584
    cudaFuncSetAttribute((const void*)agemm,
                         cudaFuncAttributeMaxDynamicSharedMemorySize, (int)SMEM_AG);
    cudaFuncSetAttribute((const void*)kv2,
                         cudaFuncAttributeMaxDynamicSharedMemorySize, (int)SMEM_AG);
    cudaFuncSetAttribute((const void*)tgemm2,
                         cudaFuncAttributeMaxDynamicSharedMemorySize, (int)SMEM_T2);

    const int GN = (NN + 127) / 128;   // 782

    conv_x_kernel<<<12500, 256>>>(x);
    trans_all<<<1216, 256>>>(wk, wv, wq, W1, W2);

    agemm<<<GN, 256, SMEM_AG>>>(
        (const __half*)pXh, (const __half*)pWQ, 1,
        (__half*)pQh, 128, 3, nullptr);

    kv2<<<dim3(GN, 1, 5), 256, SMEM_AG>>>(nbr);

    combine_ln1_kernel<<<NN / 8, 256>>>(x, g1, be1);

    agemm<<<GN, 256, SMEM_AG>>>(
        (const __half*)pHth, (const __half*)pW1, 4,
        (__half*)pFh, 512, 1, b1);

    tgemm2<<<GN, 256, SMEM_T2>>>(
        (const __half*)pFh, (const __half*)pW2,
        out, b2, (const __half*)pHth, g2, be2);
}